// round 1
// baseline (speedup 1.0000x reference)
#include <cuda_runtime.h>
#include <math.h>

#define B_    8
#define C_    256
#define H_    112
#define W_    112
#define HW_   12544
#define P_    196
#define S_    64
#define TG_   56
#define AG_   3136
#define CHW_  (C_*HW_)          // 3211264
#define NSPLIT_PS 16

// ---------------- static device scratch (no allocations allowed) ------------
__device__ float g_xn[B_*CHW_];
__device__ float g_q [B_*CHW_];
__device__ float g_k [B_*CHW_];
__device__ float g_v [B_*CHW_];
__device__ float g_qp[B_*C_*AG_];
__device__ float g_kp[B_*C_*AG_];
__device__ float g_vp[B_*C_*AG_];
__device__ float g_sp[B_*P_*P_];
__device__ float g_spart[B_*NSPLIT_PS*P_*P_];
__device__ float g_sg[(size_t)B_*AG_*AG_];      // 314 MB global scores
__device__ float g_hp[B_*CHW_];                 // patch out, then combined h (in place)
__device__ float g_hg[B_*C_*AG_];
__device__ float g_part[B_*128*2];
__device__ float g_mu[B_];
__device__ float g_rstd[B_];

static inline int cdiv(int a, int b) { return (a + b - 1) / b; }

// ---------------- GroupNorm stats ------------------------------------------
__global__ void gn_stats1(const float* __restrict__ x) {
    int b = blockIdx.y;
    const float4* xb = (const float4*)(x + (size_t)b * CHW_);
    const int n4 = CHW_ / 4;
    float s = 0.f, q = 0.f;
    for (int i = blockIdx.x * blockDim.x + threadIdx.x; i < n4; i += gridDim.x * blockDim.x) {
        float4 t = xb[i];
        s += t.x + t.y + t.z + t.w;
        q += t.x*t.x + t.y*t.y + t.z*t.z + t.w*t.w;
    }
    __shared__ float sh[2][8];
    for (int o = 16; o; o >>= 1) {
        s += __shfl_down_sync(0xffffffffu, s, o);
        q += __shfl_down_sync(0xffffffffu, q, o);
    }
    int w = threadIdx.x >> 5, l = threadIdx.x & 31;
    if (l == 0) { sh[0][w] = s; sh[1][w] = q; }
    __syncthreads();
    if (w == 0) {
        s = (l < 8) ? sh[0][l] : 0.f;
        q = (l < 8) ? sh[1][l] : 0.f;
        for (int o = 4; o; o >>= 1) {
            s += __shfl_down_sync(0xffffffffu, s, o);
            q += __shfl_down_sync(0xffffffffu, q, o);
        }
        if (l == 0) {
            g_part[(b * 128 + blockIdx.x) * 2 + 0] = s;
            g_part[(b * 128 + blockIdx.x) * 2 + 1] = q;
        }
    }
}

__global__ void gn_stats2() {
    int b = blockIdx.x, t = threadIdx.x;  // 128 threads
    float s = g_part[(b * 128 + t) * 2 + 0];
    float q = g_part[(b * 128 + t) * 2 + 1];
    __shared__ float sh[2][4];
    for (int o = 16; o; o >>= 1) {
        s += __shfl_down_sync(0xffffffffu, s, o);
        q += __shfl_down_sync(0xffffffffu, q, o);
    }
    if ((t & 31) == 0) { sh[0][t >> 5] = s; sh[1][t >> 5] = q; }
    __syncthreads();
    if (t == 0) {
        s = sh[0][0] + sh[0][1] + sh[0][2] + sh[0][3];
        q = sh[1][0] + sh[1][1] + sh[1][2] + sh[1][3];
        float mu  = s / (float)CHW_;
        float var = q / (float)CHW_ - mu * mu;
        g_mu[b]   = mu;
        g_rstd[b] = rsqrtf(var + 1e-5f);
    }
}

__global__ void gn_apply(const float* __restrict__ x,
                         const float* __restrict__ gw,
                         const float* __restrict__ gb) {
    int i = blockIdx.x * blockDim.x + threadIdx.x;   // float4 index
    const int n4 = B_ * CHW_ / 4;
    if (i >= n4) return;
    int c = (i / (HW_ / 4)) % C_;
    int b = i / (CHW_ / 4);
    float a  = g_rstd[b] * gw[c];
    float bb = gb[c] - g_mu[b] * a;
    float4 t = ((const float4*)x)[i];
    t.x = t.x * a + bb; t.y = t.y * a + bb;
    t.z = t.z * a + bb; t.w = t.w * a + bb;
    ((float4*)g_xn)[i] = t;
}

// ---------------- generic tiled fp32 GEMM ----------------------------------
// OPA==0: A is [M,K] row-major;  OPA==1: A is [K,M] row-major
// OPB==0: B is [K,N] row-major;  OPB==1: B is [N,K] row-major
// C written at C + z*sC, compact [M,N]. z = batch*nsplit + split (split-K).
template<int OPA, int OPB, bool BIAS, bool ADDSRC>
__global__ void __launch_bounds__(256) gemm_k(
    const float* __restrict__ A, size_t sA,
    const float* __restrict__ B, size_t sB,
    float* __restrict__ C, size_t sC,
    const float* __restrict__ bias,
    const float* __restrict__ src, size_t sSrc,
    int M, int N, int K, int nsplit, float alpha)
{
    __shared__ __align__(16) float As[16][64];
    __shared__ __align__(16) float Bs[16][64];

    int z = blockIdx.z;
    int batch = z / nsplit;
    int split = z - batch * nsplit;
    int Kc = (K + nsplit - 1) / nsplit;
    int kb = split * Kc;
    int ke = min(K, kb + Kc);
    int m0 = blockIdx.y * 64;
    int n0 = blockIdx.x * 64;
    const float* Ab = A + (size_t)batch * sA;
    const float* Bb = B + (size_t)batch * sB;
    int tid = threadIdx.x;
    int tx = tid & 15, ty = tid >> 4;
    float acc[4][4] = {};

    for (int kt = kb; kt < ke; kt += 16) {
        if (OPA == 0) {
            int m  = tid >> 2;
            int kv = (tid & 3) * 4;
            float4 t = make_float4(0.f, 0.f, 0.f, 0.f);
            if (m0 + m < M && kt + kv < ke)
                t = *(const float4*)(Ab + (size_t)(m0 + m) * K + kt + kv);
            As[kv + 0][m] = t.x; As[kv + 1][m] = t.y;
            As[kv + 2][m] = t.z; As[kv + 3][m] = t.w;
        } else {
            int k  = tid >> 4;
            int mv = (tid & 15) * 4;
            float4 t = make_float4(0.f, 0.f, 0.f, 0.f);
            if (kt + k < ke && m0 + mv < M)
                t = *(const float4*)(Ab + (size_t)(kt + k) * M + m0 + mv);
            *(float4*)&As[k][mv] = t;
        }
        if (OPB == 0) {
            int k  = tid >> 4;
            int nv = (tid & 15) * 4;
            float4 t = make_float4(0.f, 0.f, 0.f, 0.f);
            if (kt + k < ke && n0 + nv < N)
                t = *(const float4*)(Bb + (size_t)(kt + k) * N + n0 + nv);
            *(float4*)&Bs[k][nv] = t;
        } else {
            int n  = tid >> 2;
            int kv = (tid & 3) * 4;
            float4 t = make_float4(0.f, 0.f, 0.f, 0.f);
            if (n0 + n < N && kt + kv < ke)
                t = *(const float4*)(Bb + (size_t)(n0 + n) * K + kt + kv);
            Bs[kv + 0][n] = t.x; Bs[kv + 1][n] = t.y;
            Bs[kv + 2][n] = t.z; Bs[kv + 3][n] = t.w;
        }
        __syncthreads();
        #pragma unroll
        for (int kk = 0; kk < 16; kk++) {
            float4 a = *(const float4*)&As[kk][ty * 4];
            float4 b = *(const float4*)&Bs[kk][tx * 4];
            float av[4] = {a.x, a.y, a.z, a.w};
            float bv[4] = {b.x, b.y, b.z, b.w};
            #pragma unroll
            for (int i = 0; i < 4; i++)
                #pragma unroll
                for (int j = 0; j < 4; j++)
                    acc[i][j] += av[i] * bv[j];
        }
        __syncthreads();
    }

    float* Cb = C + (size_t)z * sC;
    #pragma unroll
    for (int i = 0; i < 4; i++) {
        int m = m0 + ty * 4 + i;
        if (m >= M) continue;
        #pragma unroll
        for (int j = 0; j < 4; j++) {
            int n = n0 + tx * 4 + j;
            if (n >= N) continue;
            float val = alpha * acc[i][j];
            if (BIAS)   val += bias[m];
            if (ADDSRC) val += src[(size_t)batch * sSrc + (size_t)m * N + n];
            Cb[(size_t)m * N + n] = val;
        }
    }
}

__global__ void reduce_splits(const float* __restrict__ part, float* __restrict__ out,
                              int MN, int nsplit) {
    int i = blockIdx.x * blockDim.x + threadIdx.x;
    int b = blockIdx.y;
    if (i >= MN) return;
    float s = 0.f;
    for (int sp = 0; sp < nsplit; sp++)
        s += part[(size_t)(b * nsplit + sp) * MN + i];
    out[(size_t)b * MN + i] = s;
}

// ---------------- softmax over rows (L <= 3328) -----------------------------
__global__ void __launch_bounds__(256) softmax_rows(float* __restrict__ data, int L) {
    const int T = 256;
    float* d = data + (size_t)blockIdx.x * L;
    int tid = threadIdx.x;
    float v[13];
    float mx = -3.0e38f;
    #pragma unroll
    for (int j = 0; j < 13; j++) {
        int i = tid + j * T;
        if (i < L) { v[j] = d[i]; mx = fmaxf(mx, v[j]); }
    }
    __shared__ float sh[8];
    float t = mx;
    for (int o = 16; o; o >>= 1) t = fmaxf(t, __shfl_xor_sync(0xffffffffu, t, o));
    if ((tid & 31) == 0) sh[tid >> 5] = t;
    __syncthreads();
    float rmx = fmaxf(fmaxf(fmaxf(sh[0], sh[1]), fmaxf(sh[2], sh[3])),
                      fmaxf(fmaxf(sh[4], sh[5]), fmaxf(sh[6], sh[7])));
    __syncthreads();
    float sum = 0.f;
    #pragma unroll
    for (int j = 0; j < 13; j++) {
        int i = tid + j * T;
        if (i < L) { v[j] = __expf(v[j] - rmx); sum += v[j]; }
    }
    float ts = sum;
    for (int o = 16; o; o >>= 1) ts += __shfl_xor_sync(0xffffffffu, ts, o);
    if ((tid & 31) == 0) sh[tid >> 5] = ts;
    __syncthreads();
    float tot = sh[0] + sh[1] + sh[2] + sh[3] + sh[4] + sh[5] + sh[6] + sh[7];
    float inv = 1.0f / tot;
    #pragma unroll
    for (int j = 0; j < 13; j++) {
        int i = tid + j * T;
        if (i < L) d[i] = v[j] * inv;
    }
}

// ---------------- 2x2 average pool 112 -> 56 --------------------------------
__global__ void pool2x2(const float* __restrict__ in, float* __restrict__ out) {
    int i = blockIdx.x * blockDim.x + threadIdx.x;
    if (i >= B_ * C_ * AG_) return;
    int xo = i % TG_;
    int yo = (i / TG_) % TG_;
    int bc = i / AG_;
    const float* p = in + (size_t)bc * HW_ + (size_t)(2 * yo) * W_ + 2 * xo;
    out[i] = 0.25f * (p[0] + p[1] + p[W_] + p[W_ + 1]);
}

// ---------------- bilinear 56->112 upsample + weighted combine (in place) ---
__global__ void combine_upsample() {
    int i = blockIdx.x * blockDim.x + threadIdx.x;
    if (i >= B_ * CHW_) return;
    int xo = i % W_;
    int yo = (i / W_) % H_;
    int bc = i / HW_;
    int ya, yb; float wya, wyb;
    if (yo & 1) { ya = yo >> 1; yb = min(ya + 1, TG_ - 1); wya = 0.75f; wyb = 0.25f; }
    else        { yb = yo >> 1; ya = max(yb - 1, 0);       wya = 0.25f; wyb = 0.75f; }
    int xa, xb; float wxa, wxb;
    if (xo & 1) { xa = xo >> 1; xb = min(xa + 1, TG_ - 1); wxa = 0.75f; wxb = 0.25f; }
    else        { xb = xo >> 1; xa = max(xb - 1, 0);       wxa = 0.25f; wxb = 0.75f; }
    const float* hg = g_hg + (size_t)bc * AG_;
    float g = wya * (wxa * hg[ya * TG_ + xa] + wxb * hg[ya * TG_ + xb])
            + wyb * (wxa * hg[yb * TG_ + xa] + wxb * hg[yb * TG_ + xb]);
    g_hp[i] = 0.75f * g_hp[i] + 0.25f * g;
}

// ---------------- launcher ---------------------------------------------------
extern "C" void kernel_launch(void* const* d_in, const int* in_sizes, int n_in,
                              void* d_out, int out_size) {
    const float* x  = (const float*)d_in[0];
    const float* gw = (const float*)d_in[1];
    const float* gb = (const float*)d_in[2];
    const float* wq = (const float*)d_in[3];
    const float* bq = (const float*)d_in[4];
    const float* wk = (const float*)d_in[5];
    const float* bk = (const float*)d_in[6];
    const float* wv = (const float*)d_in[7];
    const float* bv = (const float*)d_in[8];
    const float* wp = (const float*)d_in[9];
    float* out = (float*)d_out;

    float* p_xn;  cudaGetSymbolAddress((void**)&p_xn,  g_xn);
    float* p_q;   cudaGetSymbolAddress((void**)&p_q,   g_q);
    float* p_k;   cudaGetSymbolAddress((void**)&p_k,   g_k);
    float* p_v;   cudaGetSymbolAddress((void**)&p_v,   g_v);
    float* p_qp;  cudaGetSymbolAddress((void**)&p_qp,  g_qp);
    float* p_kp;  cudaGetSymbolAddress((void**)&p_kp,  g_kp);
    float* p_vp;  cudaGetSymbolAddress((void**)&p_vp,  g_vp);
    float* p_sp;  cudaGetSymbolAddress((void**)&p_sp,  g_sp);
    float* p_spt; cudaGetSymbolAddress((void**)&p_spt, g_spart);
    float* p_sg;  cudaGetSymbolAddress((void**)&p_sg,  g_sg);
    float* p_hp;  cudaGetSymbolAddress((void**)&p_hp,  g_hp);
    float* p_hg;  cudaGetSymbolAddress((void**)&p_hg,  g_hg);

    // 1) GroupNorm
    gn_stats1<<<dim3(128, B_), 256>>>(x);
    gn_stats2<<<B_, 128>>>();
    gn_apply<<<cdiv(B_ * CHW_ / 4, 256), 256>>>(x, gw, gb);

    // 2) Q/K/V projections: [256x256] x [256x12544] per batch
    dim3 gproj(cdiv(HW_, 64), cdiv(C_, 64), B_);
    gemm_k<0,0,true,false><<<gproj, 256>>>(wq, 0, p_xn, CHW_, p_q, CHW_,
                                           bq, nullptr, 0, C_, HW_, C_, 1, 1.f);
    gemm_k<0,0,true,false><<<gproj, 256>>>(wk, 0, p_xn, CHW_, p_k, CHW_,
                                           bk, nullptr, 0, C_, HW_, C_, 1, 1.f);
    gemm_k<0,0,true,false><<<gproj, 256>>>(wv, 0, p_xn, CHW_, p_v, CHW_,
                                           bv, nullptr, 0, C_, HW_, C_, 1, 1.f);

    // 3) 2x2 pools
    pool2x2<<<cdiv(B_ * C_ * AG_, 256), 256>>>(p_q, p_qp);
    pool2x2<<<cdiv(B_ * C_ * AG_, 256), 256>>>(p_k, p_kp);
    pool2x2<<<cdiv(B_ * C_ * AG_, 256), 256>>>(p_v, p_vp);

    // 4) Patch attention: scores (TN, K=16384, split-K) -> softmax -> out (NT)
    dim3 gps(cdiv(P_, 64), cdiv(P_, 64), B_ * NSPLIT_PS);
    gemm_k<1,0,false,false><<<gps, 256>>>(p_q, CHW_, p_k, CHW_,
                                          p_spt, (size_t)P_ * P_,
                                          nullptr, nullptr, 0,
                                          P_, P_, C_ * S_, NSPLIT_PS, 1.f / 128.f);
    reduce_splits<<<dim3(cdiv(P_ * P_, 256), B_), 256>>>(p_spt, p_sp, P_ * P_, NSPLIT_PS);
    softmax_rows<<<B_ * P_, 256>>>(p_sp, P_);
    dim3 gpo(cdiv(P_, 64), cdiv(C_ * S_, 64), B_);
    gemm_k<0,1,false,false><<<gpo, 256>>>(p_v, CHW_, p_sp, (size_t)P_ * P_,
                                          p_hp, CHW_, nullptr, nullptr, 0,
                                          C_ * S_, P_, P_, 1, 1.f);

    // 5) Global attention: scores (TN, K=256) -> softmax -> out (NT)
    dim3 ggs(cdiv(AG_, 64), cdiv(AG_, 64), B_);
    gemm_k<1,0,false,false><<<ggs, 256>>>(p_qp, (size_t)C_ * AG_, p_kp, (size_t)C_ * AG_,
                                          p_sg, (size_t)AG_ * AG_,
                                          nullptr, nullptr, 0,
                                          AG_, AG_, C_, 1, 1.f / 16.f);
    softmax_rows<<<B_ * AG_, 256>>>(p_sg, AG_);
    dim3 ggo(cdiv(AG_, 64), cdiv(C_, 64), B_);
    gemm_k<0,1,false,false><<<ggo, 256>>>(p_vp, (size_t)C_ * AG_, p_sg, (size_t)AG_ * AG_,
                                          p_hg, (size_t)C_ * AG_, nullptr, nullptr, 0,
                                          C_, AG_, AG_, 1, 1.f);

    // 6) combine 0.75*patch + 0.25*bilinear_up(global) in place into g_hp
    combine_upsample<<<cdiv(B_ * CHW_, 256), 256>>>();

    // 7) out = x + Wproj @ h
    gemm_k<0,0,false,true><<<gproj, 256>>>(wp, 0, p_hp, CHW_, out, CHW_,
                                           nullptr, x, CHW_, C_, HW_, C_, 1, 1.f);
}

// round 4
// speedup vs baseline: 1.4727x; 1.4727x over previous
#include <cuda_runtime.h>
#include <math.h>
#include <stdint.h>

#define B_    8
#define C_    256
#define H_    112
#define W_    112
#define HW_   12544
#define P_    196
#define S_    64
#define TG_   56
#define AG_   3136
#define CHW_  (C_*HW_)          // 3211264
#define NSPLIT_PS 8

// ---------------- static device scratch (no allocations allowed) ------------
__device__ float g_xn[B_*CHW_];
__device__ float g_q [B_*CHW_];
__device__ float g_k [B_*CHW_];
__device__ float g_v [B_*CHW_];
__device__ float g_qp[B_*C_*AG_];
__device__ float g_kp[B_*C_*AG_];
__device__ float g_vp[B_*C_*AG_];
__device__ float g_sp[B_*P_*P_];
__device__ float g_spart[B_*NSPLIT_PS*P_*P_];
__device__ float g_sg[(size_t)B_*AG_*AG_];      // 314 MB global scores
__device__ float g_hp[B_*CHW_];                 // patch out, then combined h (in place)
__device__ float g_hg[B_*C_*AG_];
__device__ float g_part[B_*128*2];
__device__ float g_mu[B_];
__device__ float g_rstd[B_];

static inline int cdiv(int a, int b) { return (a + b - 1) / b; }

// float -> tf32 bit pattern (b32 destination register)
__device__ __forceinline__ float to_tf32(float x) {
    uint32_t y;
    asm("cvt.rna.tf32.f32 %0, %1;" : "=r"(y) : "f"(x));
    return __uint_as_float(y);
}

// ---------------- GroupNorm stats ------------------------------------------
__global__ void gn_stats1(const float* __restrict__ x) {
    int b = blockIdx.y;
    const float4* xb = (const float4*)(x + (size_t)b * CHW_);
    const int n4 = CHW_ / 4;
    float s = 0.f, q = 0.f;
    for (int i = blockIdx.x * blockDim.x + threadIdx.x; i < n4; i += gridDim.x * blockDim.x) {
        float4 t = xb[i];
        s += t.x + t.y + t.z + t.w;
        q += t.x*t.x + t.y*t.y + t.z*t.z + t.w*t.w;
    }
    __shared__ float sh[2][8];
    for (int o = 16; o; o >>= 1) {
        s += __shfl_down_sync(0xffffffffu, s, o);
        q += __shfl_down_sync(0xffffffffu, q, o);
    }
    int w = threadIdx.x >> 5, l = threadIdx.x & 31;
    if (l == 0) { sh[0][w] = s; sh[1][w] = q; }
    __syncthreads();
    if (w == 0) {
        s = (l < 8) ? sh[0][l] : 0.f;
        q = (l < 8) ? sh[1][l] : 0.f;
        for (int o = 4; o; o >>= 1) {
            s += __shfl_down_sync(0xffffffffu, s, o);
            q += __shfl_down_sync(0xffffffffu, q, o);
        }
        if (l == 0) {
            g_part[(b * 128 + blockIdx.x) * 2 + 0] = s;
            g_part[(b * 128 + blockIdx.x) * 2 + 1] = q;
        }
    }
}

__global__ void gn_stats2() {
    int b = blockIdx.x, t = threadIdx.x;  // 128 threads
    float s = g_part[(b * 128 + t) * 2 + 0];
    float q = g_part[(b * 128 + t) * 2 + 1];
    __shared__ float sh[2][4];
    for (int o = 16; o; o >>= 1) {
        s += __shfl_down_sync(0xffffffffu, s, o);
        q += __shfl_down_sync(0xffffffffu, q, o);
    }
    if ((t & 31) == 0) { sh[0][t >> 5] = s; sh[1][t >> 5] = q; }
    __syncthreads();
    if (t == 0) {
        s = sh[0][0] + sh[0][1] + sh[0][2] + sh[0][3];
        q = sh[1][0] + sh[1][1] + sh[1][2] + sh[1][3];
        float mu  = s / (float)CHW_;
        float var = q / (float)CHW_ - mu * mu;
        g_mu[b]   = mu;
        g_rstd[b] = rsqrtf(var + 1e-5f);
    }
}

__global__ void gn_apply(const float* __restrict__ x,
                         const float* __restrict__ gw,
                         const float* __restrict__ gb) {
    int i = blockIdx.x * blockDim.x + threadIdx.x;   // float4 index
    const int n4 = B_ * CHW_ / 4;
    if (i >= n4) return;
    int c = (i / (HW_ / 4)) % C_;
    int b = i / (CHW_ / 4);
    float a  = g_rstd[b] * gw[c];
    float bb = gb[c] - g_mu[b] * a;
    float4 t = ((const float4*)x)[i];
    t.x = t.x * a + bb; t.y = t.y * a + bb;
    t.z = t.z * a + bb; t.w = t.w * a + bb;
    ((float4*)g_xn)[i] = t;
}

// ---------------- tf32 tensor-core GEMM -------------------------------------
// Block tile 128x128, K-chunk 32. 8 warps of 64(M)x32(N).
// OPA==0: A [M,K] row-major;  OPA==1: A [K,M] row-major
// OPB==0: B [K,N] row-major;  OPB==1: B [N,K] row-major
// C written at C + z*sC, compact [M,N]; z = batch*nsplit + split (split-K).
#define SMS 136   // smem row stride (floats): conflict-free fragment reads

__device__ __forceinline__ void mma_tf32(float* c, const uint32_t* a, const uint32_t* b) {
    asm volatile(
        "mma.sync.aligned.m16n8k8.row.col.f32.tf32.tf32.f32 "
        "{%0,%1,%2,%3}, {%4,%5,%6,%7}, {%8,%9}, {%0,%1,%2,%3};\n"
        : "+f"(c[0]), "+f"(c[1]), "+f"(c[2]), "+f"(c[3])
        : "r"(a[0]), "r"(a[1]), "r"(a[2]), "r"(a[3]), "r"(b[0]), "r"(b[1]));
}

template<int OPA, int OPB, bool BIAS, bool ADDSRC>
__global__ void __launch_bounds__(256, 2) gemm_tc(
    const float* __restrict__ A, size_t sA,
    const float* __restrict__ B, size_t sB,
    float* __restrict__ C, size_t sC,
    const float* __restrict__ bias,
    const float* __restrict__ src, size_t sSrc,
    int M, int N, int K, int nsplit, float alpha)
{
    __shared__ __align__(16) float As[32][SMS];
    __shared__ __align__(16) float Bs[32][SMS];

    int z = blockIdx.z;
    int batch = z / nsplit;
    int split = z - batch * nsplit;
    int Kc = (K + nsplit - 1) / nsplit;
    int kb = split * Kc;
    int ke = min(K, kb + Kc);
    int m0 = blockIdx.y * 128;
    int n0 = blockIdx.x * 128;
    const float* Ab = A + (size_t)batch * sA;
    const float* Bb = B + (size_t)batch * sB;

    int tid  = threadIdx.x;
    int wid  = tid >> 5;
    int lane = tid & 31;
    int g  = lane >> 2;       // 0..7
    int tg = lane & 3;        // 0..3
    int warp_m = wid >> 2;    // 0..1 -> 64 rows each
    int warp_n = wid & 3;     // 0..3 -> 32 cols each
    int wm0 = warp_m * 64;
    int wn0 = warp_n * 32;

    float acc[4][4][4];
    #pragma unroll
    for (int i = 0; i < 4; i++)
        #pragma unroll
        for (int j = 0; j < 4; j++)
            #pragma unroll
            for (int r = 0; r < 4; r++) acc[i][j][r] = 0.f;

    for (int kt = kb; kt < ke; kt += 32) {
        // ---- stage A -> As[k][m] ----
        if (OPA == 0) {
            // A[m][k], k contiguous: float4 along k, scatter stores
            #pragma unroll
            for (int it = 0; it < 4; it++) {
                int idx = tid + it * 256;            // 0..1023
                int m  = idx >> 3;                   // 0..127
                int kv = (idx & 7) * 4;              // 0,4,..28
                float4 t = make_float4(0.f,0.f,0.f,0.f);
                if (m0 + m < M) {
                    if (kt + kv + 3 < ke) {
                        t = *(const float4*)(Ab + (size_t)(m0 + m) * K + kt + kv);
                    } else {
                        float* tp = &t.x;
                        #pragma unroll
                        for (int j = 0; j < 4; j++)
                            if (kt + kv + j < ke) tp[j] = Ab[(size_t)(m0 + m) * K + kt + kv + j];
                    }
                }
                As[kv + 0][m] = to_tf32(t.x); As[kv + 1][m] = to_tf32(t.y);
                As[kv + 2][m] = to_tf32(t.z); As[kv + 3][m] = to_tf32(t.w);
            }
        } else {
            // A[k][m], m contiguous: float4 along m, direct stores
            #pragma unroll
            for (int it = 0; it < 4; it++) {
                int idx = tid + it * 256;
                int k  = idx >> 5;                   // 0..31
                int mv = (idx & 31) * 4;             // 0..124
                float4 t = make_float4(0.f,0.f,0.f,0.f);
                if (kt + k < ke) {
                    if (m0 + mv + 3 < M) {
                        t = *(const float4*)(Ab + (size_t)(kt + k) * M + m0 + mv);
                    } else {
                        float* tp = &t.x;
                        #pragma unroll
                        for (int j = 0; j < 4; j++)
                            if (m0 + mv + j < M) tp[j] = Ab[(size_t)(kt + k) * M + m0 + mv + j];
                    }
                }
                t.x = to_tf32(t.x); t.y = to_tf32(t.y);
                t.z = to_tf32(t.z); t.w = to_tf32(t.w);
                *(float4*)&As[k][mv] = t;
            }
        }
        // ---- stage B -> Bs[k][n] ----
        if (OPB == 0) {
            // B[k][n], n contiguous
            #pragma unroll
            for (int it = 0; it < 4; it++) {
                int idx = tid + it * 256;
                int k  = idx >> 5;
                int nv = (idx & 31) * 4;
                float4 t = make_float4(0.f,0.f,0.f,0.f);
                if (kt + k < ke) {
                    if (n0 + nv + 3 < N) {
                        t = *(const float4*)(Bb + (size_t)(kt + k) * N + n0 + nv);
                    } else {
                        float* tp = &t.x;
                        #pragma unroll
                        for (int j = 0; j < 4; j++)
                            if (n0 + nv + j < N) tp[j] = Bb[(size_t)(kt + k) * N + n0 + nv + j];
                    }
                }
                t.x = to_tf32(t.x); t.y = to_tf32(t.y);
                t.z = to_tf32(t.z); t.w = to_tf32(t.w);
                *(float4*)&Bs[k][nv] = t;
            }
        } else {
            // B[n][k], k contiguous: float4 along k, scatter stores
            #pragma unroll
            for (int it = 0; it < 4; it++) {
                int idx = tid + it * 256;
                int n  = idx >> 3;
                int kv = (idx & 7) * 4;
                float4 t = make_float4(0.f,0.f,0.f,0.f);
                if (n0 + n < N) {
                    if (kt + kv + 3 < ke) {
                        t = *(const float4*)(Bb + (size_t)(n0 + n) * K + kt + kv);
                    } else {
                        float* tp = &t.x;
                        #pragma unroll
                        for (int j = 0; j < 4; j++)
                            if (kt + kv + j < ke) tp[j] = Bb[(size_t)(n0 + n) * K + kt + kv + j];
                    }
                }
                Bs[kv + 0][n] = to_tf32(t.x); Bs[kv + 1][n] = to_tf32(t.y);
                Bs[kv + 2][n] = to_tf32(t.z); Bs[kv + 3][n] = to_tf32(t.w);
            }
        }
        __syncthreads();

        // ---- compute: 4 k-steps of 8 ----
        #pragma unroll
        for (int ks = 0; ks < 4; ks++) {
            int k0 = ks * 8;
            uint32_t afr[4][4], bfr[4][2];
            #pragma unroll
            for (int mf = 0; mf < 4; mf++) {
                int rm = wm0 + mf * 16;
                afr[mf][0] = __float_as_uint(As[k0 + tg    ][rm + g    ]);
                afr[mf][1] = __float_as_uint(As[k0 + tg    ][rm + g + 8]);
                afr[mf][2] = __float_as_uint(As[k0 + tg + 4][rm + g    ]);
                afr[mf][3] = __float_as_uint(As[k0 + tg + 4][rm + g + 8]);
            }
            #pragma unroll
            for (int nf = 0; nf < 4; nf++) {
                int cn = wn0 + nf * 8;
                bfr[nf][0] = __float_as_uint(Bs[k0 + tg    ][cn + g]);
                bfr[nf][1] = __float_as_uint(Bs[k0 + tg + 4][cn + g]);
            }
            #pragma unroll
            for (int mf = 0; mf < 4; mf++)
                #pragma unroll
                for (int nf = 0; nf < 4; nf++)
                    mma_tf32(acc[mf][nf], afr[mf], bfr[nf]);
        }
        __syncthreads();
    }

    // ---- epilogue ----
    float* Cb = C + (size_t)z * sC;
    #pragma unroll
    for (int mf = 0; mf < 4; mf++) {
        int r0 = m0 + wm0 + mf * 16 + g;
        int r1 = r0 + 8;
        float bias0 = 0.f, bias1 = 0.f;
        if (BIAS) {
            if (r0 < M) bias0 = bias[r0];
            if (r1 < M) bias1 = bias[r1];
        }
        #pragma unroll
        for (int nf = 0; nf < 4; nf++) {
            int cn = n0 + wn0 + nf * 8 + 2 * tg;
            #pragma unroll
            for (int j = 0; j < 2; j++) {
                int n = cn + j;
                if (n >= N) continue;
                if (r0 < M) {
                    float v = alpha * acc[mf][nf][j];
                    if (BIAS)   v += bias0;
                    if (ADDSRC) v += src[(size_t)batch * sSrc + (size_t)r0 * N + n];
                    Cb[(size_t)r0 * N + n] = v;
                }
                if (r1 < M) {
                    float v = alpha * acc[mf][nf][2 + j];
                    if (BIAS)   v += bias1;
                    if (ADDSRC) v += src[(size_t)batch * sSrc + (size_t)r1 * N + n];
                    Cb[(size_t)r1 * N + n] = v;
                }
            }
        }
    }
}

__global__ void reduce_splits(const float* __restrict__ part, float* __restrict__ out,
                              int MN, int nsplit) {
    int i = blockIdx.x * blockDim.x + threadIdx.x;
    int b = blockIdx.y;
    if (i >= MN) return;
    float s = 0.f;
    for (int sp = 0; sp < nsplit; sp++)
        s += part[(size_t)(b * nsplit + sp) * MN + i];
    out[(size_t)b * MN + i] = s;
}

// ---------------- softmax over rows (L <= 3328) -----------------------------
__global__ void __launch_bounds__(256) softmax_rows(float* __restrict__ data, int L) {
    const int T = 256;
    float* d = data + (size_t)blockIdx.x * L;
    int tid = threadIdx.x;
    float v[13];
    float mx = -3.0e38f;
    #pragma unroll
    for (int j = 0; j < 13; j++) {
        int i = tid + j * T;
        if (i < L) { v[j] = d[i]; mx = fmaxf(mx, v[j]); }
    }
    __shared__ float sh[8];
    float t = mx;
    for (int o = 16; o; o >>= 1) t = fmaxf(t, __shfl_xor_sync(0xffffffffu, t, o));
    if ((tid & 31) == 0) sh[tid >> 5] = t;
    __syncthreads();
    float rmx = fmaxf(fmaxf(fmaxf(sh[0], sh[1]), fmaxf(sh[2], sh[3])),
                      fmaxf(fmaxf(sh[4], sh[5]), fmaxf(sh[6], sh[7])));
    __syncthreads();
    float sum = 0.f;
    #pragma unroll
    for (int j = 0; j < 13; j++) {
        int i = tid + j * T;
        if (i < L) { v[j] = __expf(v[j] - rmx); sum += v[j]; }
    }
    float ts = sum;
    for (int o = 16; o; o >>= 1) ts += __shfl_xor_sync(0xffffffffu, ts, o);
    if ((tid & 31) == 0) sh[tid >> 5] = ts;
    __syncthreads();
    float tot = sh[0] + sh[1] + sh[2] + sh[3] + sh[4] + sh[5] + sh[6] + sh[7];
    float inv = 1.0f / tot;
    #pragma unroll
    for (int j = 0; j < 13; j++) {
        int i = tid + j * T;
        if (i < L) d[i] = v[j] * inv;
    }
}

// ---------------- 2x2 average pool 112 -> 56 --------------------------------
__global__ void pool2x2(const float* __restrict__ in, float* __restrict__ out) {
    int i = blockIdx.x * blockDim.x + threadIdx.x;
    if (i >= B_ * C_ * AG_) return;
    int xo = i % TG_;
    int yo = (i / TG_) % TG_;
    int bc = i / AG_;
    const float* p = in + (size_t)bc * HW_ + (size_t)(2 * yo) * W_ + 2 * xo;
    out[i] = 0.25f * (p[0] + p[1] + p[W_] + p[W_ + 1]);
}

// ---------------- bilinear 56->112 upsample + weighted combine (in place) ---
__global__ void combine_upsample() {
    int i = blockIdx.x * blockDim.x + threadIdx.x;
    if (i >= B_ * CHW_) return;
    int xo = i % W_;
    int yo = (i / W_) % H_;
    int bc = i / HW_;
    int ya, yb; float wya, wyb;
    if (yo & 1) { ya = yo >> 1; yb = min(ya + 1, TG_ - 1); wya = 0.75f; wyb = 0.25f; }
    else        { yb = yo >> 1; ya = max(yb - 1, 0);       wya = 0.25f; wyb = 0.75f; }
    int xa, xb; float wxa, wxb;
    if (xo & 1) { xa = xo >> 1; xb = min(xa + 1, TG_ - 1); wxa = 0.75f; wxb = 0.25f; }
    else        { xb = xo >> 1; xa = max(xb - 1, 0);       wxa = 0.25f; wxb = 0.75f; }
    const float* hg = g_hg + (size_t)bc * AG_;
    float g = wya * (wxa * hg[ya * TG_ + xa] + wxb * hg[ya * TG_ + xb])
            + wyb * (wxa * hg[yb * TG_ + xa] + wxb * hg[yb * TG_ + xb]);
    g_hp[i] = 0.75f * g_hp[i] + 0.25f * g;
}

// ---------------- launcher ---------------------------------------------------
extern "C" void kernel_launch(void* const* d_in, const int* in_sizes, int n_in,
                              void* d_out, int out_size) {
    const float* x  = (const float*)d_in[0];
    const float* gw = (const float*)d_in[1];
    const float* gb = (const float*)d_in[2];
    const float* wq = (const float*)d_in[3];
    const float* bq = (const float*)d_in[4];
    const float* wk = (const float*)d_in[5];
    const float* bk = (const float*)d_in[6];
    const float* wv = (const float*)d_in[7];
    const float* bv = (const float*)d_in[8];
    const float* wp = (const float*)d_in[9];
    float* out = (float*)d_out;

    float* p_xn;  cudaGetSymbolAddress((void**)&p_xn,  g_xn);
    float* p_q;   cudaGetSymbolAddress((void**)&p_q,   g_q);
    float* p_k;   cudaGetSymbolAddress((void**)&p_k,   g_k);
    float* p_v;   cudaGetSymbolAddress((void**)&p_v,   g_v);
    float* p_qp;  cudaGetSymbolAddress((void**)&p_qp,  g_qp);
    float* p_kp;  cudaGetSymbolAddress((void**)&p_kp,  g_kp);
    float* p_vp;  cudaGetSymbolAddress((void**)&p_vp,  g_vp);
    float* p_sp;  cudaGetSymbolAddress((void**)&p_sp,  g_sp);
    float* p_spt; cudaGetSymbolAddress((void**)&p_spt, g_spart);
    float* p_sg;  cudaGetSymbolAddress((void**)&p_sg,  g_sg);
    float* p_hp;  cudaGetSymbolAddress((void**)&p_hp,  g_hp);
    float* p_hg;  cudaGetSymbolAddress((void**)&p_hg,  g_hg);

    // 1) GroupNorm
    gn_stats1<<<dim3(128, B_), 256>>>(x);
    gn_stats2<<<B_, 128>>>();
    gn_apply<<<cdiv(B_ * CHW_ / 4, 256), 256>>>(x, gw, gb);

    // 2) Q/K/V projections: [256x256] x [256x12544] per batch
    dim3 gproj(cdiv(HW_, 128), cdiv(C_, 128), B_);
    gemm_tc<0,0,true,false><<<gproj, 256>>>(wq, 0, p_xn, CHW_, p_q, CHW_,
                                            bq, nullptr, 0, C_, HW_, C_, 1, 1.f);
    gemm_tc<0,0,true,false><<<gproj, 256>>>(wk, 0, p_xn, CHW_, p_k, CHW_,
                                            bk, nullptr, 0, C_, HW_, C_, 1, 1.f);
    gemm_tc<0,0,true,false><<<gproj, 256>>>(wv, 0, p_xn, CHW_, p_v, CHW_,
                                            bv, nullptr, 0, C_, HW_, C_, 1, 1.f);

    // 3) 2x2 pools
    pool2x2<<<cdiv(B_ * C_ * AG_, 256), 256>>>(p_q, p_qp);
    pool2x2<<<cdiv(B_ * C_ * AG_, 256), 256>>>(p_k, p_kp);
    pool2x2<<<cdiv(B_ * C_ * AG_, 256), 256>>>(p_v, p_vp);

    // 4) Patch attention: scores (TN, K=16384, split-K) -> softmax -> out (NT)
    dim3 gps(cdiv(P_, 128), cdiv(P_, 128), B_ * NSPLIT_PS);
    gemm_tc<1,0,false,false><<<gps, 256>>>(p_q, CHW_, p_k, CHW_,
                                           p_spt, (size_t)P_ * P_,
                                           nullptr, nullptr, 0,
                                           P_, P_, C_ * S_, NSPLIT_PS, 1.f / 128.f);
    reduce_splits<<<dim3(cdiv(P_ * P_, 256), B_), 256>>>(p_spt, p_sp, P_ * P_, NSPLIT_PS);
    softmax_rows<<<B_ * P_, 256>>>(p_sp, P_);
    dim3 gpo(cdiv(P_, 128), cdiv(C_ * S_, 128), B_);
    gemm_tc<0,1,false,false><<<gpo, 256>>>(p_v, CHW_, p_sp, (size_t)P_ * P_,
                                           p_hp, CHW_, nullptr, nullptr, 0,
                                           C_ * S_, P_, P_, 1, 1.f);

    // 5) Global attention: scores (TN, K=256) -> softmax -> out (NT)
    dim3 ggs(cdiv(AG_, 128), cdiv(AG_, 128), B_);
    gemm_tc<1,0,false,false><<<ggs, 256>>>(p_qp, (size_t)C_ * AG_, p_kp, (size_t)C_ * AG_,
                                           p_sg, (size_t)AG_ * AG_,
                                           nullptr, nullptr, 0,
                                           AG_, AG_, C_, 1, 1.f / 16.f);
    softmax_rows<<<B_ * AG_, 256>>>(p_sg, AG_);
    dim3 ggo(cdiv(AG_, 128), cdiv(C_, 128), B_);
    gemm_tc<0,1,false,false><<<ggo, 256>>>(p_vp, (size_t)C_ * AG_, p_sg, (size_t)AG_ * AG_,
                                           p_hg, (size_t)C_ * AG_, nullptr, nullptr, 0,
                                           C_, AG_, AG_, 1, 1.f);

    // 6) combine 0.75*patch + 0.25*bilinear_up(global) in place into g_hp
    combine_upsample<<<cdiv(B_ * CHW_, 256), 256>>>();

    // 7) out = x + Wproj @ h
    gemm_tc<0,0,false,true><<<gproj, 256>>>(wp, 0, p_hp, CHW_, out, CHW_,
                                            nullptr, x, CHW_, C_, HW_, C_, 1, 1.f);
}

// round 9
// speedup vs baseline: 2.7400x; 1.8606x over previous
#include <cuda_runtime.h>
#include <math.h>
#include <stdint.h>

#define B_    8
#define C_    256
#define H_    112
#define W_    112
#define HW_   12544
#define P_    196
#define S_    64
#define TG_   56
#define AG_   3136
#define CHW_  (C_*HW_)          // 3211264
#define NSPLIT_PS 8

// ---------------- static device scratch (no allocations allowed) ------------
__device__ float g_xn[B_*CHW_];
__device__ float g_q [B_*CHW_];
__device__ float g_k [B_*CHW_];
__device__ float g_v [B_*CHW_];
__device__ float g_qp[B_*C_*AG_];
__device__ float g_kp[B_*C_*AG_];
__device__ float g_vp[B_*C_*AG_];
__device__ float g_sp[B_*P_*P_];
__device__ float g_spart[B_*NSPLIT_PS*P_*P_];
__device__ float g_sg[(size_t)B_*AG_*AG_];      // 314 MB global scores
__device__ float g_hp[B_*CHW_];                 // patch out, then combined h (in place)
__device__ float g_hg[B_*C_*AG_];
__device__ float g_part[B_*128*2];
__device__ float g_mu[B_];
__device__ float g_rstd[B_];

static inline int cdiv(int a, int b) { return (a + b - 1) / b; }

__device__ __forceinline__ uint32_t smem_u32(const void* p) {
    return (uint32_t)__cvta_generic_to_shared(p);
}
__device__ __forceinline__ void cp16(uint32_t dst, const float* src, bool ok) {
    int sz = ok ? 16 : 0;
    asm volatile("cp.async.cg.shared.global [%0], [%1], 16, %2;\n"
                 :: "r"(dst), "l"(src), "r"(sz));
}

// ---------------- GroupNorm stats ------------------------------------------
__global__ void gn_stats1(const float* __restrict__ x) {
    int b = blockIdx.y;
    const float4* xb = (const float4*)(x + (size_t)b * CHW_);
    const int n4 = CHW_ / 4;
    float s = 0.f, q = 0.f;
    for (int i = blockIdx.x * blockDim.x + threadIdx.x; i < n4; i += gridDim.x * blockDim.x) {
        float4 t = xb[i];
        s += t.x + t.y + t.z + t.w;
        q += t.x*t.x + t.y*t.y + t.z*t.z + t.w*t.w;
    }
    __shared__ float sh[2][8];
    for (int o = 16; o; o >>= 1) {
        s += __shfl_down_sync(0xffffffffu, s, o);
        q += __shfl_down_sync(0xffffffffu, q, o);
    }
    int w = threadIdx.x >> 5, l = threadIdx.x & 31;
    if (l == 0) { sh[0][w] = s; sh[1][w] = q; }
    __syncthreads();
    if (w == 0) {
        s = (l < 8) ? sh[0][l] : 0.f;
        q = (l < 8) ? sh[1][l] : 0.f;
        for (int o = 4; o; o >>= 1) {
            s += __shfl_down_sync(0xffffffffu, s, o);
            q += __shfl_down_sync(0xffffffffu, q, o);
        }
        if (l == 0) {
            g_part[(b * 128 + blockIdx.x) * 2 + 0] = s;
            g_part[(b * 128 + blockIdx.x) * 2 + 1] = q;
        }
    }
}

__global__ void gn_stats2() {
    int b = blockIdx.x, t = threadIdx.x;  // 128 threads
    float s = g_part[(b * 128 + t) * 2 + 0];
    float q = g_part[(b * 128 + t) * 2 + 1];
    __shared__ float sh[2][4];
    for (int o = 16; o; o >>= 1) {
        s += __shfl_down_sync(0xffffffffu, s, o);
        q += __shfl_down_sync(0xffffffffu, q, o);
    }
    if ((t & 31) == 0) { sh[0][t >> 5] = s; sh[1][t >> 5] = q; }
    __syncthreads();
    if (t == 0) {
        s = sh[0][0] + sh[0][1] + sh[0][2] + sh[0][3];
        q = sh[1][0] + sh[1][1] + sh[1][2] + sh[1][3];
        float mu  = s / (float)CHW_;
        float var = q / (float)CHW_ - mu * mu;
        g_mu[b]   = mu;
        g_rstd[b] = rsqrtf(var + 1e-5f);
    }
}

__global__ void gn_apply(const float* __restrict__ x,
                         const float* __restrict__ gw,
                         const float* __restrict__ gb) {
    int i = blockIdx.x * blockDim.x + threadIdx.x;   // float4 index
    const int n4 = B_ * CHW_ / 4;
    if (i >= n4) return;
    int c = (i / (HW_ / 4)) % C_;
    int b = i / (CHW_ / 4);
    float a  = g_rstd[b] * gw[c];
    float bb = gb[c] - g_mu[b] * a;
    float4 t = ((const float4*)x)[i];
    t.x = t.x * a + bb; t.y = t.y * a + bb;
    t.z = t.z * a + bb; t.w = t.w * a + bb;
    ((float4*)g_xn)[i] = t;
}

// ---------------- tf32 tensor-core GEMM, 2-stage cp.async pipeline ----------
// Block tile 128x128, K-chunk 16. 8 warps of 64(M)x32(N).
// OPA==0: A [M,K] row-major  (staged MN-major, stride 20)
// OPA==1: A [K,M] row-major  (staged K-major,  stride 136)
// OPB==0: B [K,N] row-major  (staged K-major,  stride 136)
// OPB==1: B [N,K] row-major  (staged MN-major, stride 20)
// C written at C + z*sC, compact [M,N]; z = batch*nsplit + split (split-K).

__device__ __forceinline__ void mma_tf32(float* c, const uint32_t* a, const uint32_t* b) {
    asm volatile(
        "mma.sync.aligned.m16n8k8.row.col.f32.tf32.tf32.f32 "
        "{%0,%1,%2,%3}, {%4,%5,%6,%7}, {%8,%9}, {%0,%1,%2,%3};\n"
        : "+f"(c[0]), "+f"(c[1]), "+f"(c[2]), "+f"(c[3])
        : "r"(a[0]), "r"(a[1]), "r"(a[2]), "r"(a[3]), "r"(b[0]), "r"(b[1]));
}

template<int OPA, int OPB, bool BIAS, bool ADDSRC>
__global__ void __launch_bounds__(256, 2) gemm_tc(
    const float* __restrict__ A, size_t sA,
    const float* __restrict__ B, size_t sB,
    float* __restrict__ C, size_t sC,
    const float* __restrict__ bias,
    const float* __restrict__ src, size_t sSrc,
    int M, int N, int K, int nsplit, float alpha)
{
    constexpr int KC  = 16;
    constexpr int AST = (OPA == 0) ? 20 : 136;
    constexpr int BST = (OPB == 1) ? 20 : 136;
    constexpr int ASZ = (OPA == 0) ? 128 * 20 : KC * 136;
    constexpr int BSZ = (OPB == 1) ? 128 * 20 : KC * 136;
    __shared__ __align__(16) float smem[2 * (ASZ + BSZ)];

    int z = blockIdx.z;
    int batch = z / nsplit;
    int split = z - batch * nsplit;
    int Kc = (K + nsplit - 1) / nsplit;
    int kb = split * Kc;
    int ke = min(K, kb + Kc);
    int m0 = blockIdx.y * 128;
    int n0 = blockIdx.x * 128;
    const float* Ab = A + (size_t)batch * sA;
    const float* Bb = B + (size_t)batch * sB;

    int tid  = threadIdx.x;
    int wid  = tid >> 5;
    int lane = tid & 31;
    int g  = lane >> 2;       // 0..7
    int tg = lane & 3;        // 0..3
    int wm0 = (wid >> 2) * 64;
    int wn0 = (wid & 3) * 32;

    auto load_stage = [&](int kt, int s) {
        float* As = smem + s * (ASZ + BSZ);
        float* Bs = As + ASZ;
        // A tile: 512 chunks of 16B (128x16 MN-major, or 16x128 K-major)
        #pragma unroll
        for (int it = 0; it < 2; it++) {
            int c = tid + it * 256;
            if (OPA == 0) {
                int row = c >> 2, kc = (c & 3) * 4;
                bool ok = (m0 + row < M) && (kt + kc < ke);
                const float* p = ok ? Ab + (size_t)(m0 + row) * K + kt + kc : Ab;
                cp16(smem_u32(As + row * AST + kc), p, ok);
            } else {
                int k = c >> 5, col = (c & 31) * 4;
                bool ok = (kt + k < ke) && (m0 + col < M);
                const float* p = ok ? Ab + (size_t)(kt + k) * M + m0 + col : Ab;
                cp16(smem_u32(As + k * AST + col), p, ok);
            }
        }
        // B tile: 512 chunks of 16B
        #pragma unroll
        for (int it = 0; it < 2; it++) {
            int c = tid + it * 256;
            if (OPB == 0) {
                int k = c >> 5, col = (c & 31) * 4;
                bool ok = (kt + k < ke) && (n0 + col < N);
                const float* p = ok ? Bb + (size_t)(kt + k) * N + n0 + col : Bb;
                cp16(smem_u32(Bs + k * BST + col), p, ok);
            } else {
                int row = c >> 2, kc = (c & 3) * 4;
                bool ok = (n0 + row < N) && (kt + kc < ke);
                const float* p = ok ? Bb + (size_t)(n0 + row) * K + kt + kc : Bb;
                cp16(smem_u32(Bs + row * BST + kc), p, ok);
            }
        }
    };

    float acc[4][4][4];
    #pragma unroll
    for (int i = 0; i < 4; i++)
        #pragma unroll
        for (int j = 0; j < 4; j++)
            #pragma unroll
            for (int r = 0; r < 4; r++) acc[i][j][r] = 0.f;

    load_stage(kb, 0);
    asm volatile("cp.async.commit_group;\n");
    int stage = 0;

    for (int kt = kb; kt < ke; kt += KC) {
        asm volatile("cp.async.wait_group 0;\n");
        __syncthreads();
        int ktn = kt + KC;
        if (ktn < ke) {
            load_stage(ktn, stage ^ 1);
            asm volatile("cp.async.commit_group;\n");
        }
        float* As = smem + stage * (ASZ + BSZ);
        float* Bs = As + ASZ;
        #pragma unroll
        for (int ks = 0; ks < 2; ks++) {
            int k0 = ks * 8;
            uint32_t afr[4][4], bfr[4][2];
            #pragma unroll
            for (int mf = 0; mf < 4; mf++) {
                int rm = wm0 + mf * 16;
                if (OPA == 0) {
                    afr[mf][0] = __float_as_uint(As[(rm + g    ) * AST + k0 + tg    ]);
                    afr[mf][1] = __float_as_uint(As[(rm + g + 8) * AST + k0 + tg    ]);
                    afr[mf][2] = __float_as_uint(As[(rm + g    ) * AST + k0 + tg + 4]);
                    afr[mf][3] = __float_as_uint(As[(rm + g + 8) * AST + k0 + tg + 4]);
                } else {
                    afr[mf][0] = __float_as_uint(As[(k0 + tg    ) * AST + rm + g    ]);
                    afr[mf][1] = __float_as_uint(As[(k0 + tg    ) * AST + rm + g + 8]);
                    afr[mf][2] = __float_as_uint(As[(k0 + tg + 4) * AST + rm + g    ]);
                    afr[mf][3] = __float_as_uint(As[(k0 + tg + 4) * AST + rm + g + 8]);
                }
            }
            #pragma unroll
            for (int nf = 0; nf < 4; nf++) {
                int cn = wn0 + nf * 8;
                if (OPB == 1) {
                    bfr[nf][0] = __float_as_uint(Bs[(cn + g) * BST + k0 + tg    ]);
                    bfr[nf][1] = __float_as_uint(Bs[(cn + g) * BST + k0 + tg + 4]);
                } else {
                    bfr[nf][0] = __float_as_uint(Bs[(k0 + tg    ) * BST + cn + g]);
                    bfr[nf][1] = __float_as_uint(Bs[(k0 + tg + 4) * BST + cn + g]);
                }
            }
            #pragma unroll
            for (int mf = 0; mf < 4; mf++)
                #pragma unroll
                for (int nf = 0; nf < 4; nf++)
                    mma_tf32(acc[mf][nf], afr[mf], bfr[nf]);
        }
        __syncthreads();
        stage ^= 1;
    }

    // ---- epilogue ----
    float* Cb = C + (size_t)z * sC;
    #pragma unroll
    for (int mf = 0; mf < 4; mf++) {
        int r0 = m0 + wm0 + mf * 16 + g;
        int r1 = r0 + 8;
        float bias0 = 0.f, bias1 = 0.f;
        if (BIAS) {
            if (r0 < M) bias0 = bias[r0];
            if (r1 < M) bias1 = bias[r1];
        }
        #pragma unroll
        for (int nf = 0; nf < 4; nf++) {
            int cn = n0 + wn0 + nf * 8 + 2 * tg;
            #pragma unroll
            for (int j = 0; j < 2; j++) {
                int n = cn + j;
                if (n >= N) continue;
                if (r0 < M) {
                    float v = alpha * acc[mf][nf][j];
                    if (BIAS)   v += bias0;
                    if (ADDSRC) v += src[(size_t)batch * sSrc + (size_t)r0 * N + n];
                    Cb[(size_t)r0 * N + n] = v;
                }
                if (r1 < M) {
                    float v = alpha * acc[mf][nf][2 + j];
                    if (BIAS)   v += bias1;
                    if (ADDSRC) v += src[(size_t)batch * sSrc + (size_t)r1 * N + n];
                    Cb[(size_t)r1 * N + n] = v;
                }
            }
        }
    }
}

__global__ void reduce_splits(const float* __restrict__ part, float* __restrict__ out,
                              int MN, int nsplit) {
    int i = blockIdx.x * blockDim.x + threadIdx.x;
    int b = blockIdx.y;
    if (i >= MN) return;
    float s = 0.f;
    for (int sp = 0; sp < nsplit; sp++)
        s += part[(size_t)(b * nsplit + sp) * MN + i];
    out[(size_t)b * MN + i] = s;
}

// ---------------- softmax over rows (L <= 3328) -----------------------------
__global__ void __launch_bounds__(256) softmax_rows(float* __restrict__ data, int L) {
    const int T = 256;
    float* d = data + (size_t)blockIdx.x * L;
    int tid = threadIdx.x;
    float v[13];
    float mx = -3.0e38f;
    #pragma unroll
    for (int j = 0; j < 13; j++) {
        int i = tid + j * T;
        if (i < L) { v[j] = d[i]; mx = fmaxf(mx, v[j]); }
    }
    __shared__ float sh[8];
    float t = mx;
    for (int o = 16; o; o >>= 1) t = fmaxf(t, __shfl_xor_sync(0xffffffffu, t, o));
    if ((tid & 31) == 0) sh[tid >> 5] = t;
    __syncthreads();
    float rmx = fmaxf(fmaxf(fmaxf(sh[0], sh[1]), fmaxf(sh[2], sh[3])),
                      fmaxf(fmaxf(sh[4], sh[5]), fmaxf(sh[6], sh[7])));
    __syncthreads();
    float sum = 0.f;
    #pragma unroll
    for (int j = 0; j < 13; j++) {
        int i = tid + j * T;
        if (i < L) { v[j] = __expf(v[j] - rmx); sum += v[j]; }
    }
    float ts = sum;
    for (int o = 16; o; o >>= 1) ts += __shfl_xor_sync(0xffffffffu, ts, o);
    if ((tid & 31) == 0) sh[tid >> 5] = ts;
    __syncthreads();
    float tot = sh[0] + sh[1] + sh[2] + sh[3] + sh[4] + sh[5] + sh[6] + sh[7];
    float inv = 1.0f / tot;
    #pragma unroll
    for (int j = 0; j < 13; j++) {
        int i = tid + j * T;
        if (i < L) d[i] = v[j] * inv;
    }
}

// ---------------- 2x2 average pool 112 -> 56 --------------------------------
__global__ void pool2x2(const float* __restrict__ in, float* __restrict__ out) {
    int i = blockIdx.x * blockDim.x + threadIdx.x;
    if (i >= B_ * C_ * AG_) return;
    int xo = i % TG_;
    int yo = (i / TG_) % TG_;
    int bc = i / AG_;
    const float* p = in + (size_t)bc * HW_ + (size_t)(2 * yo) * W_ + 2 * xo;
    out[i] = 0.25f * (p[0] + p[1] + p[W_] + p[W_ + 1]);
}

// ---------------- bilinear 56->112 upsample + weighted combine (in place) ---
__global__ void combine_upsample() {
    int i = blockIdx.x * blockDim.x + threadIdx.x;
    if (i >= B_ * CHW_) return;
    int xo = i % W_;
    int yo = (i / W_) % H_;
    int bc = i / HW_;
    int ya, yb; float wya, wyb;
    if (yo & 1) { ya = yo >> 1; yb = min(ya + 1, TG_ - 1); wya = 0.75f; wyb = 0.25f; }
    else        { yb = yo >> 1; ya = max(yb - 1, 0);       wya = 0.25f; wyb = 0.75f; }
    int xa, xb; float wxa, wxb;
    if (xo & 1) { xa = xo >> 1; xb = min(xa + 1, TG_ - 1); wxa = 0.75f; wxb = 0.25f; }
    else        { xb = xo >> 1; xa = max(xb - 1, 0);       wxa = 0.25f; wxb = 0.75f; }
    const float* hg = g_hg + (size_t)bc * AG_;
    float g = wya * (wxa * hg[ya * TG_ + xa] + wxb * hg[ya * TG_ + xb])
            + wyb * (wxa * hg[yb * TG_ + xa] + wxb * hg[yb * TG_ + xb]);
    g_hp[i] = 0.75f * g_hp[i] + 0.25f * g;
}

// ---------------- launcher ---------------------------------------------------
extern "C" void kernel_launch(void* const* d_in, const int* in_sizes, int n_in,
                              void* d_out, int out_size) {
    const float* x  = (const float*)d_in[0];
    const float* gw = (const float*)d_in[1];
    const float* gb = (const float*)d_in[2];
    const float* wq = (const float*)d_in[3];
    const float* bq = (const float*)d_in[4];
    const float* wk = (const float*)d_in[5];
    const float* bk = (const float*)d_in[6];
    const float* wv = (const float*)d_in[7];
    const float* bv = (const float*)d_in[8];
    const float* wp = (const float*)d_in[9];
    float* out = (float*)d_out;

    float* p_xn;  cudaGetSymbolAddress((void**)&p_xn,  g_xn);
    float* p_q;   cudaGetSymbolAddress((void**)&p_q,   g_q);
    float* p_k;   cudaGetSymbolAddress((void**)&p_k,   g_k);
    float* p_v;   cudaGetSymbolAddress((void**)&p_v,   g_v);
    float* p_qp;  cudaGetSymbolAddress((void**)&p_qp,  g_qp);
    float* p_kp;  cudaGetSymbolAddress((void**)&p_kp,  g_kp);
    float* p_vp;  cudaGetSymbolAddress((void**)&p_vp,  g_vp);
    float* p_sp;  cudaGetSymbolAddress((void**)&p_sp,  g_sp);
    float* p_spt; cudaGetSymbolAddress((void**)&p_spt, g_spart);
    float* p_sg;  cudaGetSymbolAddress((void**)&p_sg,  g_sg);
    float* p_hp;  cudaGetSymbolAddress((void**)&p_hp,  g_hp);
    float* p_hg;  cudaGetSymbolAddress((void**)&p_hg,  g_hg);

    // 1) GroupNorm
    gn_stats1<<<dim3(128, B_), 256>>>(x);
    gn_stats2<<<B_, 128>>>();
    gn_apply<<<cdiv(B_ * CHW_ / 4, 256), 256>>>(x, gw, gb);

    // 2) Q/K/V projections: [256x256] x [256x12544] per batch
    dim3 gproj(cdiv(HW_, 128), cdiv(C_, 128), B_);
    gemm_tc<0,0,true,false><<<gproj, 256>>>(wq, 0, p_xn, CHW_, p_q, CHW_,
                                            bq, nullptr, 0, C_, HW_, C_, 1, 1.f);
    gemm_tc<0,0,true,false><<<gproj, 256>>>(wk, 0, p_xn, CHW_, p_k, CHW_,
                                            bk, nullptr, 0, C_, HW_, C_, 1, 1.f);
    gemm_tc<0,0,true,false><<<gproj, 256>>>(wv, 0, p_xn, CHW_, p_v, CHW_,
                                            bv, nullptr, 0, C_, HW_, C_, 1, 1.f);

    // 3) 2x2 pools
    pool2x2<<<cdiv(B_ * C_ * AG_, 256), 256>>>(p_q, p_qp);
    pool2x2<<<cdiv(B_ * C_ * AG_, 256), 256>>>(p_k, p_kp);
    pool2x2<<<cdiv(B_ * C_ * AG_, 256), 256>>>(p_v, p_vp);

    // 4) Patch attention: scores (TN, K=16384, split-K) -> softmax -> out (NT)
    dim3 gps(cdiv(P_, 128), cdiv(P_, 128), B_ * NSPLIT_PS);
    gemm_tc<1,0,false,false><<<gps, 256>>>(p_q, CHW_, p_k, CHW_,
                                           p_spt, (size_t)P_ * P_,
                                           nullptr, nullptr, 0,
                                           P_, P_, C_ * S_, NSPLIT_PS, 1.f / 128.f);
    reduce_splits<<<dim3(cdiv(P_ * P_, 256), B_), 256>>>(p_spt, p_sp, P_ * P_, NSPLIT_PS);
    softmax_rows<<<B_ * P_, 256>>>(p_sp, P_);
    dim3 gpo(cdiv(P_, 128), cdiv(C_ * S_, 128), B_);
    gemm_tc<0,1,false,false><<<gpo, 256>>>(p_v, CHW_, p_sp, (size_t)P_ * P_,
                                           p_hp, CHW_, nullptr, nullptr, 0,
                                           C_ * S_, P_, P_, 1, 1.f);

    // 5) Global attention: scores (TN, K=256) -> softmax -> out (NT)
    dim3 ggs(cdiv(AG_, 128), cdiv(AG_, 128), B_);
    gemm_tc<1,0,false,false><<<ggs, 256>>>(p_qp, (size_t)C_ * AG_, p_kp, (size_t)C_ * AG_,
                                           p_sg, (size_t)AG_ * AG_,
                                           nullptr, nullptr, 0,
                                           AG_, AG_, C_, 1, 1.f / 16.f);
    softmax_rows<<<B_ * AG_, 256>>>(p_sg, AG_);
    dim3 ggo(cdiv(AG_, 128), cdiv(C_, 128), B_);
    gemm_tc<0,1,false,false><<<ggo, 256>>>(p_vp, (size_t)C_ * AG_, p_sg, (size_t)AG_ * AG_,
                                           p_hg, (size_t)C_ * AG_, nullptr, nullptr, 0,
                                           C_, AG_, AG_, 1, 1.f);

    // 6) combine 0.75*patch + 0.25*bilinear_up(global) in place into g_hp
    combine_upsample<<<cdiv(B_ * CHW_, 256), 256>>>();

    // 7) out = x + Wproj @ h
    gemm_tc<0,0,false,true><<<gproj, 256>>>(wp, 0, p_hp, CHW_, out, CHW_,
                                            nullptr, x, CHW_, C_, HW_, C_, 1, 1.f);
}

// round 11
// speedup vs baseline: 3.2472x; 1.1851x over previous
#include <cuda_runtime.h>
#include <math.h>
#include <stdint.h>

#define B_    8
#define C_    256
#define H_    112
#define W_    112
#define HW_   12544
#define P_    196
#define S_    64
#define TG_   56
#define AG_   3136
#define CHW_  (C_*HW_)          // 3211264
#define NSPLIT_PS 8

// ---------------- static device scratch (no allocations allowed) ------------
__device__ float g_xn[B_*CHW_];
__device__ float g_q [B_*CHW_];
__device__ float g_k [B_*CHW_];
__device__ float g_v [B_*CHW_];
__device__ float g_qp[B_*C_*AG_];
__device__ float g_kp[B_*C_*AG_];
__device__ float g_vp[B_*C_*AG_];
__device__ float g_sp[B_*P_*P_];
__device__ float g_spart[B_*NSPLIT_PS*P_*P_];
__device__ float g_sg[(size_t)B_*AG_*AG_];      // E = exp(scores), 314 MB
__device__ float g_hp[B_*CHW_];
__device__ float g_hg[B_*C_*AG_];
__device__ float g_z [B_*AG_];                  // softmax denominators
__device__ float g_part[B_*128*2];
__device__ float g_mu[B_];
__device__ float g_rstd[B_];

static inline int cdiv(int a, int b) { return (a + b - 1) / b; }

__device__ __forceinline__ uint32_t smem_u32(const void* p) {
    return (uint32_t)__cvta_generic_to_shared(p);
}
__device__ __forceinline__ void cp16(uint32_t dst, const float* src, bool ok) {
    int sz = ok ? 16 : 0;
    asm volatile("cp.async.cg.shared.global [%0], [%1], 16, %2;\n"
                 :: "r"(dst), "l"(src), "r"(sz));
}

// ---------------- GroupNorm ------------------------------------------------
__global__ void gn_stats1(const float* __restrict__ x) {
    int b = blockIdx.y;
    const float4* xb = (const float4*)(x + (size_t)b * CHW_);
    const int n4 = CHW_ / 4;
    float s = 0.f, q = 0.f;
    for (int i = blockIdx.x * blockDim.x + threadIdx.x; i < n4; i += gridDim.x * blockDim.x) {
        float4 t = xb[i];
        s += t.x + t.y + t.z + t.w;
        q += t.x*t.x + t.y*t.y + t.z*t.z + t.w*t.w;
    }
    __shared__ float sh[2][8];
    for (int o = 16; o; o >>= 1) {
        s += __shfl_down_sync(0xffffffffu, s, o);
        q += __shfl_down_sync(0xffffffffu, q, o);
    }
    int w = threadIdx.x >> 5, l = threadIdx.x & 31;
    if (l == 0) { sh[0][w] = s; sh[1][w] = q; }
    __syncthreads();
    if (w == 0) {
        s = (l < 8) ? sh[0][l] : 0.f;
        q = (l < 8) ? sh[1][l] : 0.f;
        for (int o = 4; o; o >>= 1) {
            s += __shfl_down_sync(0xffffffffu, s, o);
            q += __shfl_down_sync(0xffffffffu, q, o);
        }
        if (l == 0) {
            g_part[(b * 128 + blockIdx.x) * 2 + 0] = s;
            g_part[(b * 128 + blockIdx.x) * 2 + 1] = q;
        }
    }
}

__global__ void gn_stats2() {
    int b = blockIdx.x, t = threadIdx.x;  // 128 threads
    float s = g_part[(b * 128 + t) * 2 + 0];
    float q = g_part[(b * 128 + t) * 2 + 1];
    __shared__ float sh[2][4];
    for (int o = 16; o; o >>= 1) {
        s += __shfl_down_sync(0xffffffffu, s, o);
        q += __shfl_down_sync(0xffffffffu, q, o);
    }
    if ((t & 31) == 0) { sh[0][t >> 5] = s; sh[1][t >> 5] = q; }
    __syncthreads();
    if (t == 0) {
        s = sh[0][0] + sh[0][1] + sh[0][2] + sh[0][3];
        q = sh[1][0] + sh[1][1] + sh[1][2] + sh[1][3];
        float mu  = s / (float)CHW_;
        float var = q / (float)CHW_ - mu * mu;
        g_mu[b]   = mu;
        g_rstd[b] = rsqrtf(var + 1e-5f);
    }
}

__global__ void gn_apply(const float* __restrict__ x,
                         const float* __restrict__ gw,
                         const float* __restrict__ gb) {
    int i = blockIdx.x * blockDim.x + threadIdx.x;
    const int n4 = B_ * CHW_ / 4;
    if (i >= n4) return;
    int c = (i / (HW_ / 4)) % C_;
    int b = i / (CHW_ / 4);
    float a  = g_rstd[b] * gw[c];
    float bb = gb[c] - g_mu[b] * a;
    float4 t = ((const float4*)x)[i];
    t.x = t.x * a + bb; t.y = t.y * a + bb;
    t.z = t.z * a + bb; t.w = t.w * a + bb;
    ((float4*)g_xn)[i] = t;
}

__global__ void zero_buf(float* __restrict__ p, int n) {
    int i = blockIdx.x * blockDim.x + threadIdx.x;
    if (i < n) p[i] = 0.f;
}

// ---------------- tf32 tensor-core GEMM, KC=32, 2-stage cp.async -----------
// Block tile 128x128, K-chunk 32. 8 warps of 64(M)x32(N). Dynamic smem.
// OPA==0: A [M,K] rm (staged MN-major, stride 36); OPA==1: A [K,M] rm (K-major, 136)
// OPB==0: B [K,N] rm (K-major, 136);               OPB==1: B [N,K] rm (MN-major, 36)
// EXPOUT: C = exp(alpha*acc); row sums atomicAdd'ed into zptr[batch*sZ + m]
// SCALEN: C = alpha*acc * (1/zptr[batch*sZ + n])

__device__ __forceinline__ void mma_tf32(float* c, const uint32_t* a, const uint32_t* b) {
    asm volatile(
        "mma.sync.aligned.m16n8k8.row.col.f32.tf32.tf32.f32 "
        "{%0,%1,%2,%3}, {%4,%5,%6,%7}, {%8,%9}, {%0,%1,%2,%3};\n"
        : "+f"(c[0]), "+f"(c[1]), "+f"(c[2]), "+f"(c[3])
        : "r"(a[0]), "r"(a[1]), "r"(a[2]), "r"(a[3]), "r"(b[0]), "r"(b[1]));
}

template<int OPA, int OPB, bool BIAS, bool ADDSRC, bool EXPOUT, bool SCALEN>
__global__ void __launch_bounds__(256, 2) gemm_tc(
    const float* __restrict__ A, size_t sA,
    const float* __restrict__ B, size_t sB,
    float* __restrict__ C, size_t sC,
    const float* __restrict__ bias,
    const float* __restrict__ src, size_t sSrc,
    float* __restrict__ zptr, size_t sZ,
    int M, int N, int K, int nsplit, float alpha)
{
    constexpr int KC  = 32;
    constexpr int AST = (OPA == 0) ? 36 : 136;
    constexpr int BST = (OPB == 1) ? 36 : 136;
    constexpr int ASZ = (OPA == 0) ? 128 * 36 : KC * 136;
    constexpr int BSZ = (OPB == 1) ? 128 * 36 : KC * 136;
    extern __shared__ __align__(16) float smem[];

    int z = blockIdx.z;
    int batch = z / nsplit;
    int split = z - batch * nsplit;
    int Kc = (K + nsplit - 1) / nsplit;
    int kb = split * Kc;
    int ke = min(K, kb + Kc);
    int m0 = blockIdx.y * 128;
    int n0 = blockIdx.x * 128;
    const float* Ab = A + (size_t)batch * sA;
    const float* Bb = B + (size_t)batch * sB;

    int tid  = threadIdx.x;
    int wid  = tid >> 5;
    int lane = tid & 31;
    int g  = lane >> 2;
    int tg = lane & 3;
    int wm0 = (wid >> 2) * 64;
    int wn0 = (wid & 3) * 32;

    auto load_stage = [&](int kt, int s) {
        float* As = smem + s * (ASZ + BSZ);
        float* Bs = As + ASZ;
        // A tile: 1024 chunks of 16B (128x32 MN-major, or 32x128 K-major)
        #pragma unroll
        for (int it = 0; it < 4; it++) {
            int c = tid + it * 256;
            if (OPA == 0) {
                int row = c >> 3, kc = (c & 7) * 4;
                bool ok = (m0 + row < M) && (kt + kc < ke);
                const float* p = ok ? Ab + (size_t)(m0 + row) * K + kt + kc : Ab;
                cp16(smem_u32(As + row * AST + kc), p, ok);
            } else {
                int k = c >> 5, col = (c & 31) * 4;
                bool ok = (kt + k < ke) && (m0 + col < M);
                const float* p = ok ? Ab + (size_t)(kt + k) * M + m0 + col : Ab;
                cp16(smem_u32(As + k * AST + col), p, ok);
            }
        }
        // B tile: 1024 chunks of 16B
        #pragma unroll
        for (int it = 0; it < 4; it++) {
            int c = tid + it * 256;
            if (OPB == 0) {
                int k = c >> 5, col = (c & 31) * 4;
                bool ok = (kt + k < ke) && (n0 + col < N);
                const float* p = ok ? Bb + (size_t)(kt + k) * N + n0 + col : Bb;
                cp16(smem_u32(Bs + k * BST + col), p, ok);
            } else {
                int row = c >> 3, kc = (c & 7) * 4;
                bool ok = (n0 + row < N) && (kt + kc < ke);
                const float* p = ok ? Bb + (size_t)(n0 + row) * K + kt + kc : Bb;
                cp16(smem_u32(Bs + row * BST + kc), p, ok);
            }
        }
    };

    float acc[4][4][4];
    #pragma unroll
    for (int i = 0; i < 4; i++)
        #pragma unroll
        for (int j = 0; j < 4; j++)
            #pragma unroll
            for (int r = 0; r < 4; r++) acc[i][j][r] = 0.f;

    load_stage(kb, 0);
    asm volatile("cp.async.commit_group;\n");
    int stage = 0;

    for (int kt = kb; kt < ke; kt += KC) {
        asm volatile("cp.async.wait_group 0;\n");
        __syncthreads();
        int ktn = kt + KC;
        if (ktn < ke) {
            load_stage(ktn, stage ^ 1);
            asm volatile("cp.async.commit_group;\n");
        }
        float* As = smem + stage * (ASZ + BSZ);
        float* Bs = As + ASZ;
        #pragma unroll
        for (int ks = 0; ks < 4; ks++) {
            int k0 = ks * 8;
            uint32_t afr[4][4], bfr[4][2];
            #pragma unroll
            for (int mf = 0; mf < 4; mf++) {
                int rm = wm0 + mf * 16;
                if (OPA == 0) {
                    afr[mf][0] = __float_as_uint(As[(rm + g    ) * AST + k0 + tg    ]);
                    afr[mf][1] = __float_as_uint(As[(rm + g + 8) * AST + k0 + tg    ]);
                    afr[mf][2] = __float_as_uint(As[(rm + g    ) * AST + k0 + tg + 4]);
                    afr[mf][3] = __float_as_uint(As[(rm + g + 8) * AST + k0 + tg + 4]);
                } else {
                    afr[mf][0] = __float_as_uint(As[(k0 + tg    ) * AST + rm + g    ]);
                    afr[mf][1] = __float_as_uint(As[(k0 + tg    ) * AST + rm + g + 8]);
                    afr[mf][2] = __float_as_uint(As[(k0 + tg + 4) * AST + rm + g    ]);
                    afr[mf][3] = __float_as_uint(As[(k0 + tg + 4) * AST + rm + g + 8]);
                }
            }
            #pragma unroll
            for (int nf = 0; nf < 4; nf++) {
                int cn = wn0 + nf * 8;
                if (OPB == 1) {
                    bfr[nf][0] = __float_as_uint(Bs[(cn + g) * BST + k0 + tg    ]);
                    bfr[nf][1] = __float_as_uint(Bs[(cn + g) * BST + k0 + tg + 4]);
                } else {
                    bfr[nf][0] = __float_as_uint(Bs[(k0 + tg    ) * BST + cn + g]);
                    bfr[nf][1] = __float_as_uint(Bs[(k0 + tg + 4) * BST + cn + g]);
                }
            }
            #pragma unroll
            for (int mf = 0; mf < 4; mf++)
                #pragma unroll
                for (int nf = 0; nf < 4; nf++)
                    mma_tf32(acc[mf][nf], afr[mf], bfr[nf]);
        }
        __syncthreads();
        stage ^= 1;
    }

    // ---- epilogue ----
    float* Cb = C + (size_t)z * sC;
    float rz[4][2];
    if (SCALEN) {
        #pragma unroll
        for (int nf = 0; nf < 4; nf++)
            #pragma unroll
            for (int j = 0; j < 2; j++) {
                int n = n0 + wn0 + nf * 8 + 2 * tg + j;
                rz[nf][j] = (n < N) ? __frcp_rn(zptr[(size_t)batch * sZ + n]) : 0.f;
            }
    }
    #pragma unroll
    for (int mf = 0; mf < 4; mf++) {
        int r0 = m0 + wm0 + mf * 16 + g;
        int r1 = r0 + 8;
        float bias0 = 0.f, bias1 = 0.f;
        if (BIAS) {
            if (r0 < M) bias0 = bias[r0];
            if (r1 < M) bias1 = bias[r1];
        }
        float s0 = 0.f, s1 = 0.f;
        #pragma unroll
        for (int nf = 0; nf < 4; nf++) {
            int cn = n0 + wn0 + nf * 8 + 2 * tg;
            #pragma unroll
            for (int j = 0; j < 2; j++) {
                int n = cn + j;
                if (n >= N) continue;
                if (r0 < M) {
                    float v = alpha * acc[mf][nf][j];
                    if (BIAS)   v += bias0;
                    if (ADDSRC) v += src[(size_t)batch * sSrc + (size_t)r0 * N + n];
                    if (EXPOUT) { v = __expf(v); s0 += v; }
                    if (SCALEN) v *= rz[nf][j];
                    Cb[(size_t)r0 * N + n] = v;
                }
                if (r1 < M) {
                    float v = alpha * acc[mf][nf][2 + j];
                    if (BIAS)   v += bias1;
                    if (ADDSRC) v += src[(size_t)batch * sSrc + (size_t)r1 * N + n];
                    if (EXPOUT) { v = __expf(v); s1 += v; }
                    if (SCALEN) v *= rz[nf][j];
                    Cb[(size_t)r1 * N + n] = v;
                }
            }
        }
        if (EXPOUT) {
            s0 += __shfl_xor_sync(0xffffffffu, s0, 1);
            s0 += __shfl_xor_sync(0xffffffffu, s0, 2);
            s1 += __shfl_xor_sync(0xffffffffu, s1, 1);
            s1 += __shfl_xor_sync(0xffffffffu, s1, 2);
            if (tg == 0) {
                if (r0 < M) atomicAdd(zptr + (size_t)batch * sZ + r0, s0);
                if (r1 < M) atomicAdd(zptr + (size_t)batch * sZ + r1, s1);
            }
        }
    }
}

__global__ void reduce_splits(const float* __restrict__ part, float* __restrict__ out,
                              int MN, int nsplit) {
    int i = blockIdx.x * blockDim.x + threadIdx.x;
    int b = blockIdx.y;
    if (i >= MN) return;
    float s = 0.f;
    for (int sp = 0; sp < nsplit; sp++)
        s += part[(size_t)(b * nsplit + sp) * MN + i];
    out[(size_t)b * MN + i] = s;
}

// ---------------- softmax over rows (patch path, L=196) ---------------------
__global__ void __launch_bounds__(256) softmax_rows(float* __restrict__ data, int L) {
    const int T = 256;
    float* d = data + (size_t)blockIdx.x * L;
    int tid = threadIdx.x;
    float v[13];
    float mx = -3.0e38f;
    #pragma unroll
    for (int j = 0; j < 13; j++) {
        int i = tid + j * T;
        if (i < L) { v[j] = d[i]; mx = fmaxf(mx, v[j]); }
    }
    __shared__ float sh[8];
    float t = mx;
    for (int o = 16; o; o >>= 1) t = fmaxf(t, __shfl_xor_sync(0xffffffffu, t, o));
    if ((tid & 31) == 0) sh[tid >> 5] = t;
    __syncthreads();
    float rmx = fmaxf(fmaxf(fmaxf(sh[0], sh[1]), fmaxf(sh[2], sh[3])),
                      fmaxf(fmaxf(sh[4], sh[5]), fmaxf(sh[6], sh[7])));
    __syncthreads();
    float sum = 0.f;
    #pragma unroll
    for (int j = 0; j < 13; j++) {
        int i = tid + j * T;
        if (i < L) { v[j] = __expf(v[j] - rmx); sum += v[j]; }
    }
    float ts = sum;
    for (int o = 16; o; o >>= 1) ts += __shfl_xor_sync(0xffffffffu, ts, o);
    if ((tid & 31) == 0) sh[tid >> 5] = ts;
    __syncthreads();
    float tot = sh[0] + sh[1] + sh[2] + sh[3] + sh[4] + sh[5] + sh[6] + sh[7];
    float inv = 1.0f / tot;
    #pragma unroll
    for (int j = 0; j < 13; j++) {
        int i = tid + j * T;
        if (i < L) d[i] = v[j] * inv;
    }
}

// ---------------- 2x2 average pool 112 -> 56 --------------------------------
__global__ void pool2x2(const float* __restrict__ in, float* __restrict__ out) {
    int i = blockIdx.x * blockDim.x + threadIdx.x;
    if (i >= B_ * C_ * AG_) return;
    int xo = i % TG_;
    int yo = (i / TG_) % TG_;
    int bc = i / AG_;
    const float* p = in + (size_t)bc * HW_ + (size_t)(2 * yo) * W_ + 2 * xo;
    out[i] = 0.25f * (p[0] + p[1] + p[W_] + p[W_ + 1]);
}

// ---------------- bilinear 56->112 upsample + weighted combine (in place) ---
__global__ void combine_upsample() {
    int i = blockIdx.x * blockDim.x + threadIdx.x;
    if (i >= B_ * CHW_) return;
    int xo = i % W_;
    int yo = (i / W_) % H_;
    int bc = i / HW_;
    int ya, yb; float wya, wyb;
    if (yo & 1) { ya = yo >> 1; yb = min(ya + 1, TG_ - 1); wya = 0.75f; wyb = 0.25f; }
    else        { yb = yo >> 1; ya = max(yb - 1, 0);       wya = 0.25f; wyb = 0.75f; }
    int xa, xb; float wxa, wxb;
    if (xo & 1) { xa = xo >> 1; xb = min(xa + 1, TG_ - 1); wxa = 0.75f; wxb = 0.25f; }
    else        { xb = xo >> 1; xa = max(xb - 1, 0);       wxa = 0.25f; wxb = 0.75f; }
    const float* hg = g_hg + (size_t)bc * AG_;
    float g = wya * (wxa * hg[ya * TG_ + xa] + wxb * hg[ya * TG_ + xb])
            + wyb * (wxa * hg[yb * TG_ + xa] + wxb * hg[yb * TG_ + xb]);
    g_hp[i] = 0.75f * g_hp[i] + 0.25f * g;
}

// ---------------- launcher ---------------------------------------------------
extern "C" void kernel_launch(void* const* d_in, const int* in_sizes, int n_in,
                              void* d_out, int out_size) {
    const float* x  = (const float*)d_in[0];
    const float* gw = (const float*)d_in[1];
    const float* gb = (const float*)d_in[2];
    const float* wq = (const float*)d_in[3];
    const float* bq = (const float*)d_in[4];
    const float* wk = (const float*)d_in[5];
    const float* bk = (const float*)d_in[6];
    const float* wv = (const float*)d_in[7];
    const float* bv = (const float*)d_in[8];
    const float* wp = (const float*)d_in[9];
    float* out = (float*)d_out;

    float* p_xn;  cudaGetSymbolAddress((void**)&p_xn,  g_xn);
    float* p_q;   cudaGetSymbolAddress((void**)&p_q,   g_q);
    float* p_k;   cudaGetSymbolAddress((void**)&p_k,   g_k);
    float* p_v;   cudaGetSymbolAddress((void**)&p_v,   g_v);
    float* p_qp;  cudaGetSymbolAddress((void**)&p_qp,  g_qp);
    float* p_kp;  cudaGetSymbolAddress((void**)&p_kp,  g_kp);
    float* p_vp;  cudaGetSymbolAddress((void**)&p_vp,  g_vp);
    float* p_sp;  cudaGetSymbolAddress((void**)&p_sp,  g_sp);
    float* p_spt; cudaGetSymbolAddress((void**)&p_spt, g_spart);
    float* p_sg;  cudaGetSymbolAddress((void**)&p_sg,  g_sg);
    float* p_hp;  cudaGetSymbolAddress((void**)&p_hp,  g_hp);
    float* p_hg;  cudaGetSymbolAddress((void**)&p_hg,  g_hg);
    float* p_z;   cudaGetSymbolAddress((void**)&p_z,   g_z);

    // dynamic smem sizes per layout combo (KC=32): MN-major tile 128*36, K-major 32*136
    const int SM_00 = 2 * (128*36 + 32*136) * 4;   // 71680
    const int SM_10 = 2 * (32*136 + 32*136) * 4;   // 69632
    const int SM_01 = 2 * (128*36 + 128*36) * 4;   // 73728

    cudaFuncSetAttribute(gemm_tc<0,0,true ,false,false,false>, cudaFuncAttributeMaxDynamicSharedMemorySize, SM_00);
    cudaFuncSetAttribute(gemm_tc<0,0,false,true ,false,false>, cudaFuncAttributeMaxDynamicSharedMemorySize, SM_00);
    cudaFuncSetAttribute(gemm_tc<1,0,false,false,false,false>, cudaFuncAttributeMaxDynamicSharedMemorySize, SM_10);
    cudaFuncSetAttribute(gemm_tc<1,0,false,false,true ,false>, cudaFuncAttributeMaxDynamicSharedMemorySize, SM_10);
    cudaFuncSetAttribute(gemm_tc<0,1,false,false,false,false>, cudaFuncAttributeMaxDynamicSharedMemorySize, SM_01);
    cudaFuncSetAttribute(gemm_tc<0,1,false,false,false,true >, cudaFuncAttributeMaxDynamicSharedMemorySize, SM_01);

    // 1) GroupNorm
    gn_stats1<<<dim3(128, B_), 256>>>(x);
    gn_stats2<<<B_, 128>>>();
    gn_apply<<<cdiv(B_ * CHW_ / 4, 256), 256>>>(x, gw, gb);

    // 2) Q/K/V projections
    dim3 gproj(cdiv(HW_, 128), cdiv(C_, 128), B_);
    gemm_tc<0,0,true,false,false,false><<<gproj, 256, SM_00>>>(wq, 0, p_xn, CHW_, p_q, CHW_,
                                            bq, nullptr, 0, nullptr, 0, C_, HW_, C_, 1, 1.f);
    gemm_tc<0,0,true,false,false,false><<<gproj, 256, SM_00>>>(wk, 0, p_xn, CHW_, p_k, CHW_,
                                            bk, nullptr, 0, nullptr, 0, C_, HW_, C_, 1, 1.f);
    gemm_tc<0,0,true,false,false,false><<<gproj, 256, SM_00>>>(wv, 0, p_xn, CHW_, p_v, CHW_,
                                            bv, nullptr, 0, nullptr, 0, C_, HW_, C_, 1, 1.f);

    // 3) 2x2 pools + zero Z
    pool2x2<<<cdiv(B_ * C_ * AG_, 256), 256>>>(p_q, p_qp);
    pool2x2<<<cdiv(B_ * C_ * AG_, 256), 256>>>(p_k, p_kp);
    pool2x2<<<cdiv(B_ * C_ * AG_, 256), 256>>>(p_v, p_vp);
    zero_buf<<<cdiv(B_ * AG_, 256), 256>>>(p_z, B_ * AG_);

    // 4) Patch attention: scores (split-K) -> reduce -> softmax -> AV
    dim3 gps(cdiv(P_, 128), cdiv(P_, 128), B_ * NSPLIT_PS);
    gemm_tc<1,0,false,false,false,false><<<gps, 256, SM_10>>>(p_q, CHW_, p_k, CHW_,
                                           p_spt, (size_t)P_ * P_,
                                           nullptr, nullptr, 0, nullptr, 0,
                                           P_, P_, C_ * S_, NSPLIT_PS, 1.f / 128.f);
    reduce_splits<<<dim3(cdiv(P_ * P_, 256), B_), 256>>>(p_spt, p_sp, P_ * P_, NSPLIT_PS);
    softmax_rows<<<B_ * P_, 256>>>(p_sp, P_);
    dim3 gpo(cdiv(P_, 128), cdiv(C_ * S_, 128), B_);
    gemm_tc<0,1,false,false,false,false><<<gpo, 256, SM_01>>>(p_v, CHW_, p_sp, (size_t)P_ * P_,
                                           p_hp, CHW_, nullptr, nullptr, 0, nullptr, 0,
                                           C_ * S_, P_, P_, 1, 1.f);

    // 5) Global attention: E=exp(S) + Z (fused) -> AV scaled by 1/Z (fused)
    dim3 ggs(cdiv(AG_, 128), cdiv(AG_, 128), B_);
    gemm_tc<1,0,false,false,true,false><<<ggs, 256, SM_10>>>(p_qp, (size_t)C_ * AG_, p_kp, (size_t)C_ * AG_,
                                           p_sg, (size_t)AG_ * AG_,
                                           nullptr, nullptr, 0, p_z, AG_,
                                           AG_, AG_, C_, 1, 1.f / 16.f);
    dim3 ggo(cdiv(AG_, 128), cdiv(C_, 128), B_);
    gemm_tc<0,1,false,false,false,true><<<ggo, 256, SM_01>>>(p_vp, (size_t)C_ * AG_, p_sg, (size_t)AG_ * AG_,
                                           p_hg, (size_t)C_ * AG_, nullptr, nullptr, 0, p_z, AG_,
                                           C_, AG_, AG_, 1, 1.f);

    // 6) combine 0.75*patch + 0.25*bilinear_up(global)
    combine_upsample<<<cdiv(B_ * CHW_, 256), 256>>>();

    // 7) out = x + Wproj @ h
    gemm_tc<0,0,false,true,false,false><<<gproj, 256, SM_00>>>(wp, 0, p_hp, CHW_, out, CHW_,
                                            nullptr, x, CHW_, nullptr, 0, C_, HW_, C_, 1, 1.f);
}

// round 13
// speedup vs baseline: 3.9763x; 1.2245x over previous
#include <cuda_runtime.h>
#include <cuda_bf16.h>
#include <math.h>
#include <stdint.h>

#define B_    8
#define C_    256
#define H_    112
#define W_    112
#define HW_   12544
#define P_    196
#define S_    64
#define TG_   56
#define AG_   3136
#define CHW_  (C_*HW_)          // 3211264
#define NSPLIT_PS 8

// ---------------- static device scratch (no allocations allowed) ------------
__device__ float g_xn[B_*CHW_];
__device__ float g_q [B_*CHW_];
__device__ float g_k [B_*CHW_];
__device__ float g_v [B_*CHW_];
__device__ __nv_bfloat16 g_qpt[(size_t)B_*AG_*C_];   // pooled q, transposed [AG, C]
__device__ __nv_bfloat16 g_kpt[(size_t)B_*AG_*C_];   // pooled k, transposed [AG, C]
__device__ __nv_bfloat16 g_vpb[(size_t)B_*C_*AG_];   // pooled v [C, AG]
__device__ float g_sp[B_*P_*P_];
__device__ float g_spart[B_*NSPLIT_PS*P_*P_];
__device__ __nv_bfloat16 g_sgb[(size_t)B_*AG_*AG_];  // E = exp(scores), bf16, 157 MB
__device__ float g_hp[B_*CHW_];
__device__ float g_hg[B_*C_*AG_];
__device__ float g_z [B_*AG_];                       // softmax denominators
__device__ float g_part[B_*128*2];
__device__ float g_mu[B_];
__device__ float g_rstd[B_];

static inline int cdiv(int a, int b) { return (a + b - 1) / b; }

__device__ __forceinline__ uint32_t smem_u32(const void* p) {
    return (uint32_t)__cvta_generic_to_shared(p);
}
__device__ __forceinline__ void cp16(uint32_t dst, const void* src, bool ok) {
    int sz = ok ? 16 : 0;
    asm volatile("cp.async.cg.shared.global [%0], [%1], 16, %2;\n"
                 :: "r"(dst), "l"(src), "r"(sz));
}

// ---------------- GroupNorm ------------------------------------------------
__global__ void gn_stats1(const float* __restrict__ x) {
    int b = blockIdx.y;
    const float4* xb = (const float4*)(x + (size_t)b * CHW_);
    const int n4 = CHW_ / 4;
    float s = 0.f, q = 0.f;
    for (int i = blockIdx.x * blockDim.x + threadIdx.x; i < n4; i += gridDim.x * blockDim.x) {
        float4 t = xb[i];
        s += t.x + t.y + t.z + t.w;
        q += t.x*t.x + t.y*t.y + t.z*t.z + t.w*t.w;
    }
    __shared__ float sh[2][8];
    for (int o = 16; o; o >>= 1) {
        s += __shfl_down_sync(0xffffffffu, s, o);
        q += __shfl_down_sync(0xffffffffu, q, o);
    }
    int w = threadIdx.x >> 5, l = threadIdx.x & 31;
    if (l == 0) { sh[0][w] = s; sh[1][w] = q; }
    __syncthreads();
    if (w == 0) {
        s = (l < 8) ? sh[0][l] : 0.f;
        q = (l < 8) ? sh[1][l] : 0.f;
        for (int o = 4; o; o >>= 1) {
            s += __shfl_down_sync(0xffffffffu, s, o);
            q += __shfl_down_sync(0xffffffffu, q, o);
        }
        if (l == 0) {
            g_part[(b * 128 + blockIdx.x) * 2 + 0] = s;
            g_part[(b * 128 + blockIdx.x) * 2 + 1] = q;
        }
    }
}

__global__ void gn_stats2() {
    int b = blockIdx.x, t = threadIdx.x;  // 128 threads
    float s = g_part[(b * 128 + t) * 2 + 0];
    float q = g_part[(b * 128 + t) * 2 + 1];
    __shared__ float sh[2][4];
    for (int o = 16; o; o >>= 1) {
        s += __shfl_down_sync(0xffffffffu, s, o);
        q += __shfl_down_sync(0xffffffffu, q, o);
    }
    if ((t & 31) == 0) { sh[0][t >> 5] = s; sh[1][t >> 5] = q; }
    __syncthreads();
    if (t == 0) {
        s = sh[0][0] + sh[0][1] + sh[0][2] + sh[0][3];
        q = sh[1][0] + sh[1][1] + sh[1][2] + sh[1][3];
        float mu  = s / (float)CHW_;
        float var = q / (float)CHW_ - mu * mu;
        g_mu[b]   = mu;
        g_rstd[b] = rsqrtf(var + 1e-5f);
    }
}

__global__ void gn_apply(const float* __restrict__ x,
                         const float* __restrict__ gw,
                         const float* __restrict__ gb) {
    int i = blockIdx.x * blockDim.x + threadIdx.x;
    const int n4 = B_ * CHW_ / 4;
    if (i >= n4) return;
    int c = (i / (HW_ / 4)) % C_;
    int b = i / (CHW_ / 4);
    float a  = g_rstd[b] * gw[c];
    float bb = gb[c] - g_mu[b] * a;
    float4 t = ((const float4*)x)[i];
    t.x = t.x * a + bb; t.y = t.y * a + bb;
    t.z = t.z * a + bb; t.w = t.w * a + bb;
    ((float4*)g_xn)[i] = t;
}

__global__ void zero_buf(float* __restrict__ p, int n) {
    int i = blockIdx.x * blockDim.x + threadIdx.x;
    if (i < n) p[i] = 0.f;
}

// ---------------- tf32 tensor-core GEMM, KC=32, 2-stage cp.async -----------
// (unchanged from R11 passing kernel)
__device__ __forceinline__ void mma_tf32(float* c, const uint32_t* a, const uint32_t* b) {
    asm volatile(
        "mma.sync.aligned.m16n8k8.row.col.f32.tf32.tf32.f32 "
        "{%0,%1,%2,%3}, {%4,%5,%6,%7}, {%8,%9}, {%0,%1,%2,%3};\n"
        : "+f"(c[0]), "+f"(c[1]), "+f"(c[2]), "+f"(c[3])
        : "r"(a[0]), "r"(a[1]), "r"(a[2]), "r"(a[3]), "r"(b[0]), "r"(b[1]));
}

template<int OPA, int OPB, bool BIAS, bool ADDSRC>
__global__ void __launch_bounds__(256, 2) gemm_tc(
    const float* __restrict__ A, size_t sA,
    const float* __restrict__ B, size_t sB,
    float* __restrict__ C, size_t sC,
    const float* __restrict__ bias,
    const float* __restrict__ src, size_t sSrc,
    int M, int N, int K, int nsplit, float alpha)
{
    constexpr int KC  = 32;
    constexpr int AST = (OPA == 0) ? 36 : 136;
    constexpr int BST = (OPB == 1) ? 36 : 136;
    constexpr int ASZ = (OPA == 0) ? 128 * 36 : KC * 136;
    constexpr int BSZ = (OPB == 1) ? 128 * 36 : KC * 136;
    extern __shared__ __align__(16) float smem[];

    int z = blockIdx.z;
    int batch = z / nsplit;
    int split = z - batch * nsplit;
    int Kc = (K + nsplit - 1) / nsplit;
    int kb = split * Kc;
    int ke = min(K, kb + Kc);
    int m0 = blockIdx.y * 128;
    int n0 = blockIdx.x * 128;
    const float* Ab = A + (size_t)batch * sA;
    const float* Bb = B + (size_t)batch * sB;

    int tid  = threadIdx.x;
    int wid  = tid >> 5;
    int lane = tid & 31;
    int g  = lane >> 2;
    int tg = lane & 3;
    int wm0 = (wid >> 2) * 64;
    int wn0 = (wid & 3) * 32;

    auto load_stage = [&](int kt, int s) {
        float* As = smem + s * (ASZ + BSZ);
        float* Bs = As + ASZ;
        #pragma unroll
        for (int it = 0; it < 4; it++) {
            int c = tid + it * 256;
            if (OPA == 0) {
                int row = c >> 3, kc = (c & 7) * 4;
                bool ok = (m0 + row < M) && (kt + kc < ke);
                const float* p = ok ? Ab + (size_t)(m0 + row) * K + kt + kc : Ab;
                cp16(smem_u32(As + row * AST + kc), p, ok);
            } else {
                int k = c >> 5, col = (c & 31) * 4;
                bool ok = (kt + k < ke) && (m0 + col < M);
                const float* p = ok ? Ab + (size_t)(kt + k) * M + m0 + col : Ab;
                cp16(smem_u32(As + k * AST + col), p, ok);
            }
        }
        #pragma unroll
        for (int it = 0; it < 4; it++) {
            int c = tid + it * 256;
            if (OPB == 0) {
                int k = c >> 5, col = (c & 31) * 4;
                bool ok = (kt + k < ke) && (n0 + col < N);
                const float* p = ok ? Bb + (size_t)(kt + k) * N + n0 + col : Bb;
                cp16(smem_u32(Bs + k * BST + col), p, ok);
            } else {
                int row = c >> 3, kc = (c & 7) * 4;
                bool ok = (n0 + row < N) && (kt + kc < ke);
                const float* p = ok ? Bb + (size_t)(n0 + row) * K + kt + kc : Bb;
                cp16(smem_u32(Bs + row * BST + kc), p, ok);
            }
        }
    };

    float acc[4][4][4];
    #pragma unroll
    for (int i = 0; i < 4; i++)
        #pragma unroll
        for (int j = 0; j < 4; j++)
            #pragma unroll
            for (int r = 0; r < 4; r++) acc[i][j][r] = 0.f;

    load_stage(kb, 0);
    asm volatile("cp.async.commit_group;\n");
    int stage = 0;

    for (int kt = kb; kt < ke; kt += KC) {
        asm volatile("cp.async.wait_group 0;\n");
        __syncthreads();
        int ktn = kt + KC;
        if (ktn < ke) {
            load_stage(ktn, stage ^ 1);
            asm volatile("cp.async.commit_group;\n");
        }
        float* As = smem + stage * (ASZ + BSZ);
        float* Bs = As + ASZ;
        #pragma unroll
        for (int ks = 0; ks < 4; ks++) {
            int k0 = ks * 8;
            uint32_t afr[4][4], bfr[4][2];
            #pragma unroll
            for (int mf = 0; mf < 4; mf++) {
                int rm = wm0 + mf * 16;
                if (OPA == 0) {
                    afr[mf][0] = __float_as_uint(As[(rm + g    ) * AST + k0 + tg    ]);
                    afr[mf][1] = __float_as_uint(As[(rm + g + 8) * AST + k0 + tg    ]);
                    afr[mf][2] = __float_as_uint(As[(rm + g    ) * AST + k0 + tg + 4]);
                    afr[mf][3] = __float_as_uint(As[(rm + g + 8) * AST + k0 + tg + 4]);
                } else {
                    afr[mf][0] = __float_as_uint(As[(k0 + tg    ) * AST + rm + g    ]);
                    afr[mf][1] = __float_as_uint(As[(k0 + tg    ) * AST + rm + g + 8]);
                    afr[mf][2] = __float_as_uint(As[(k0 + tg + 4) * AST + rm + g    ]);
                    afr[mf][3] = __float_as_uint(As[(k0 + tg + 4) * AST + rm + g + 8]);
                }
            }
            #pragma unroll
            for (int nf = 0; nf < 4; nf++) {
                int cn = wn0 + nf * 8;
                if (OPB == 1) {
                    bfr[nf][0] = __float_as_uint(Bs[(cn + g) * BST + k0 + tg    ]);
                    bfr[nf][1] = __float_as_uint(Bs[(cn + g) * BST + k0 + tg + 4]);
                } else {
                    bfr[nf][0] = __float_as_uint(Bs[(k0 + tg    ) * BST + cn + g]);
                    bfr[nf][1] = __float_as_uint(Bs[(k0 + tg + 4) * BST + cn + g]);
                }
            }
            #pragma unroll
            for (int mf = 0; mf < 4; mf++)
                #pragma unroll
                for (int nf = 0; nf < 4; nf++)
                    mma_tf32(acc[mf][nf], afr[mf], bfr[nf]);
        }
        __syncthreads();
        stage ^= 1;
    }

    float* Cb = C + (size_t)z * sC;
    #pragma unroll
    for (int mf = 0; mf < 4; mf++) {
        int r0 = m0 + wm0 + mf * 16 + g;
        int r1 = r0 + 8;
        float bias0 = 0.f, bias1 = 0.f;
        if (BIAS) {
            if (r0 < M) bias0 = bias[r0];
            if (r1 < M) bias1 = bias[r1];
        }
        #pragma unroll
        for (int nf = 0; nf < 4; nf++) {
            int cn = n0 + wn0 + nf * 8 + 2 * tg;
            #pragma unroll
            for (int j = 0; j < 2; j++) {
                int n = cn + j;
                if (n >= N) continue;
                if (r0 < M) {
                    float v = alpha * acc[mf][nf][j];
                    if (BIAS)   v += bias0;
                    if (ADDSRC) v += src[(size_t)batch * sSrc + (size_t)r0 * N + n];
                    Cb[(size_t)r0 * N + n] = v;
                }
                if (r1 < M) {
                    float v = alpha * acc[mf][nf][2 + j];
                    if (BIAS)   v += bias1;
                    if (ADDSRC) v += src[(size_t)batch * sSrc + (size_t)r1 * N + n];
                    Cb[(size_t)r1 * N + n] = v;
                }
            }
        }
    }
}

// ---------------- bf16 tensor-core GEMM, KC=64, 2-stage cp.async ------------
// Both operands MN-major k-contiguous bf16: A [M,K], B [N,K]. mma m16n8k16.
// EXPOUT: C (bf16) = exp(alpha*acc), row sums -> atomicAdd zptr[batch*sZ+m]
// else  : C (f32)  = alpha*acc * (SCALEN ? 1/zptr[batch*sZ+n] : 1)
__device__ __forceinline__ void mma_bf16(float* c, const uint32_t* a, const uint32_t* b) {
    asm volatile(
        "mma.sync.aligned.m16n8k16.row.col.f32.bf16.bf16.f32 "
        "{%0,%1,%2,%3}, {%4,%5,%6,%7}, {%8,%9}, {%0,%1,%2,%3};\n"
        : "+f"(c[0]), "+f"(c[1]), "+f"(c[2]), "+f"(c[3])
        : "r"(a[0]), "r"(a[1]), "r"(a[2]), "r"(a[3]), "r"(b[0]), "r"(b[1]));
}

template<bool EXPOUT, bool SCALEN>
__global__ void __launch_bounds__(256, 2) gemm_bf(
    const __nv_bfloat16* __restrict__ A, size_t sA,
    const __nv_bfloat16* __restrict__ B, size_t sB,
    void* __restrict__ Cv, size_t sC,
    float* __restrict__ zptr, size_t sZ,
    int M, int N, int K, float alpha)
{
    constexpr int KC   = 64;                 // bf16 elements per chunk
    constexpr int RSTU = 36;                 // row stride in u32 (32 data + 4 pad)
    constexpr int TILE_B = 128 * RSTU * 4;   // 18432 bytes per tile
    extern __shared__ __align__(16) char smemc[];

    int batch = blockIdx.z;
    int m0 = blockIdx.y * 128;
    int n0 = blockIdx.x * 128;
    const __nv_bfloat16* Ab = A + (size_t)batch * sA;
    const __nv_bfloat16* Bb = B + (size_t)batch * sB;

    int tid  = threadIdx.x;
    int wid  = tid >> 5;
    int lane = tid & 31;
    int g  = lane >> 2;
    int tg = lane & 3;
    int wm0 = (wid >> 2) * 64;
    int wn0 = (wid & 3) * 32;

    auto load_stage = [&](int kt, int s) {
        char* As = smemc + s * 2 * TILE_B;
        char* Bs = As + TILE_B;
        #pragma unroll
        for (int it = 0; it < 4; it++) {
            int c = tid + it * 256;
            int row = c >> 3, kc8 = (c & 7);         // chunk of 8 bf16
            bool ok = (m0 + row < M) && (kt + kc8 * 8 < K);
            const __nv_bfloat16* p = ok ? Ab + (size_t)(m0 + row) * K + kt + kc8 * 8 : Ab;
            cp16(smem_u32(As + row * (RSTU * 4) + kc8 * 16), p, ok);
        }
        #pragma unroll
        for (int it = 0; it < 4; it++) {
            int c = tid + it * 256;
            int row = c >> 3, kc8 = (c & 7);
            bool ok = (n0 + row < N) && (kt + kc8 * 8 < K);
            const __nv_bfloat16* p = ok ? Bb + (size_t)(n0 + row) * K + kt + kc8 * 8 : Bb;
            cp16(smem_u32(Bs + row * (RSTU * 4) + kc8 * 16), p, ok);
        }
    };

    float acc[4][4][4];
    #pragma unroll
    for (int i = 0; i < 4; i++)
        #pragma unroll
        for (int j = 0; j < 4; j++)
            #pragma unroll
            for (int r = 0; r < 4; r++) acc[i][j][r] = 0.f;

    load_stage(0, 0);
    asm volatile("cp.async.commit_group;\n");
    int stage = 0;

    for (int kt = 0; kt < K; kt += KC) {
        asm volatile("cp.async.wait_group 0;\n");
        __syncthreads();
        int ktn = kt + KC;
        if (ktn < K) {
            load_stage(ktn, stage ^ 1);
            asm volatile("cp.async.commit_group;\n");
        }
        const uint32_t* As32 = (const uint32_t*)(smemc + stage * 2 * TILE_B);
        const uint32_t* Bs32 = (const uint32_t*)(smemc + stage * 2 * TILE_B + TILE_B);
        #pragma unroll
        for (int ks = 0; ks < 4; ks++) {          // 4 x k16
            int ck = ks * 8;                      // u32 offset within row
            uint32_t afr[4][4], bfr[4][2];
            #pragma unroll
            for (int mf = 0; mf < 4; mf++) {
                int rm = wm0 + mf * 16;
                afr[mf][0] = As32[(rm + g    ) * RSTU + ck + tg    ];
                afr[mf][1] = As32[(rm + g + 8) * RSTU + ck + tg    ];
                afr[mf][2] = As32[(rm + g    ) * RSTU + ck + tg + 4];
                afr[mf][3] = As32[(rm + g + 8) * RSTU + ck + tg + 4];
            }
            #pragma unroll
            for (int nf = 0; nf < 4; nf++) {
                int cn = wn0 + nf * 8;
                bfr[nf][0] = Bs32[(cn + g) * RSTU + ck + tg    ];
                bfr[nf][1] = Bs32[(cn + g) * RSTU + ck + tg + 4];
            }
            #pragma unroll
            for (int mf = 0; mf < 4; mf++)
                #pragma unroll
                for (int nf = 0; nf < 4; nf++)
                    mma_bf16(acc[mf][nf], afr[mf], bfr[nf]);
        }
        __syncthreads();
        stage ^= 1;
    }

    // ---- epilogue ----
    if (EXPOUT) {
        __nv_bfloat16* Cb = (__nv_bfloat16*)Cv + (size_t)batch * sC;
        #pragma unroll
        for (int mf = 0; mf < 4; mf++) {
            int r0 = m0 + wm0 + mf * 16 + g;
            int r1 = r0 + 8;
            float s0 = 0.f, s1 = 0.f;
            #pragma unroll
            for (int nf = 0; nf < 4; nf++) {
                int n = n0 + wn0 + nf * 8 + 2 * tg;   // even; pair (n, n+1)
                if (n < N) {
                    if (r0 < M) {
                        float v0 = __expf(alpha * acc[mf][nf][0]);
                        float v1 = __expf(alpha * acc[mf][nf][1]);
                        s0 += v0 + v1;
                        __nv_bfloat162 pk; pk.x = __float2bfloat16(v0); pk.y = __float2bfloat16(v1);
                        *(__nv_bfloat162*)(Cb + (size_t)r0 * N + n) = pk;
                    }
                    if (r1 < M) {
                        float v0 = __expf(alpha * acc[mf][nf][2]);
                        float v1 = __expf(alpha * acc[mf][nf][3]);
                        s1 += v0 + v1;
                        __nv_bfloat162 pk; pk.x = __float2bfloat16(v0); pk.y = __float2bfloat16(v1);
                        *(__nv_bfloat162*)(Cb + (size_t)r1 * N + n) = pk;
                    }
                }
            }
            s0 += __shfl_xor_sync(0xffffffffu, s0, 1);
            s0 += __shfl_xor_sync(0xffffffffu, s0, 2);
            s1 += __shfl_xor_sync(0xffffffffu, s1, 1);
            s1 += __shfl_xor_sync(0xffffffffu, s1, 2);
            if (tg == 0) {
                if (r0 < M) atomicAdd(zptr + (size_t)batch * sZ + r0, s0);
                if (r1 < M) atomicAdd(zptr + (size_t)batch * sZ + r1, s1);
            }
        }
    } else {
        float* Cb = (float*)Cv + (size_t)batch * sC;
        float rz[4][2];
        #pragma unroll
        for (int nf = 0; nf < 4; nf++)
            #pragma unroll
            for (int j = 0; j < 2; j++) {
                int n = n0 + wn0 + nf * 8 + 2 * tg + j;
                rz[nf][j] = (SCALEN && n < N) ? __frcp_rn(zptr[(size_t)batch * sZ + n]) : 1.f;
            }
        #pragma unroll
        for (int mf = 0; mf < 4; mf++) {
            int r0 = m0 + wm0 + mf * 16 + g;
            int r1 = r0 + 8;
            #pragma unroll
            for (int nf = 0; nf < 4; nf++) {
                int cn = n0 + wn0 + nf * 8 + 2 * tg;
                #pragma unroll
                for (int j = 0; j < 2; j++) {
                    int n = cn + j;
                    if (n >= N) continue;
                    if (r0 < M) Cb[(size_t)r0 * N + n] = alpha * acc[mf][nf][j]     * rz[nf][j];
                    if (r1 < M) Cb[(size_t)r1 * N + n] = alpha * acc[mf][nf][2 + j] * rz[nf][j];
                }
            }
        }
    }
}

__global__ void reduce_splits(const float* __restrict__ part, float* __restrict__ out,
                              int MN, int nsplit) {
    int i = blockIdx.x * blockDim.x + threadIdx.x;
    int b = blockIdx.y;
    if (i >= MN) return;
    float s = 0.f;
    for (int sp = 0; sp < nsplit; sp++)
        s += part[(size_t)(b * nsplit + sp) * MN + i];
    out[(size_t)b * MN + i] = s;
}

// ---------------- softmax over rows (patch path, L=196) ---------------------
__global__ void __launch_bounds__(256) softmax_rows(float* __restrict__ data, int L) {
    const int T = 256;
    float* d = data + (size_t)blockIdx.x * L;
    int tid = threadIdx.x;
    float v[13];
    float mx = -3.0e38f;
    #pragma unroll
    for (int j = 0; j < 13; j++) {
        int i = tid + j * T;
        if (i < L) { v[j] = d[i]; mx = fmaxf(mx, v[j]); }
    }
    __shared__ float sh[8];
    float t = mx;
    for (int o = 16; o; o >>= 1) t = fmaxf(t, __shfl_xor_sync(0xffffffffu, t, o));
    if ((tid & 31) == 0) sh[tid >> 5] = t;
    __syncthreads();
    float rmx = fmaxf(fmaxf(fmaxf(sh[0], sh[1]), fmaxf(sh[2], sh[3])),
                      fmaxf(fmaxf(sh[4], sh[5]), fmaxf(sh[6], sh[7])));
    __syncthreads();
    float sum = 0.f;
    #pragma unroll
    for (int j = 0; j < 13; j++) {
        int i = tid + j * T;
        if (i < L) { v[j] = __expf(v[j] - rmx); sum += v[j]; }
    }
    float ts = sum;
    for (int o = 16; o; o >>= 1) ts += __shfl_xor_sync(0xffffffffu, ts, o);
    if ((tid & 31) == 0) sh[tid >> 5] = ts;
    __syncthreads();
    float tot = sh[0] + sh[1] + sh[2] + sh[3] + sh[4] + sh[5] + sh[6] + sh[7];
    float inv = 1.0f / tot;
    #pragma unroll
    for (int j = 0; j < 13; j++) {
        int i = tid + j * T;
        if (i < L) d[i] = v[j] * inv;
    }
}

// ---------------- 2x2 pool -> transposed bf16 [AG, C] ------------------------
__global__ void pool2x2_T(const float* __restrict__ in, __nv_bfloat16* __restrict__ outT) {
    __shared__ __nv_bfloat16 tile[32][33];
    int b  = blockIdx.z;
    int a0 = blockIdx.x * 32;
    int c0 = blockIdx.y * 32;
    int tx = threadIdx.x & 31;
    int ty = threadIdx.x >> 5;        // 0..7
    #pragma unroll
    for (int i = 0; i < 4; i++) {
        int cc = ty + 8 * i;
        int a = a0 + tx;
        int yo = a / TG_, xo = a % TG_;
        const float* p = in + (size_t)b * CHW_ + (size_t)(c0 + cc) * HW_
                         + (size_t)(2 * yo) * W_ + 2 * xo;
        float v = 0.25f * (p[0] + p[1] + p[W_] + p[W_ + 1]);
        tile[cc][tx] = __float2bfloat16(v);
    }
    __syncthreads();
    #pragma unroll
    for (int i = 0; i < 4; i++) {
        int rr = ty + 8 * i;
        outT[(size_t)b * AG_ * C_ + (size_t)(a0 + rr) * C_ + c0 + tx] = tile[tx][rr];
    }
}

// ---------------- 2x2 pool -> bf16 [C, AG] -----------------------------------
__global__ void pool2x2_bf(const float* __restrict__ in, __nv_bfloat16* __restrict__ out) {
    int i = blockIdx.x * blockDim.x + threadIdx.x;
    if (i >= B_ * C_ * AG_) return;
    int xo = i % TG_;
    int yo = (i / TG_) % TG_;
    int bc = i / AG_;
    const float* p = in + (size_t)bc * HW_ + (size_t)(2 * yo) * W_ + 2 * xo;
    out[i] = __float2bfloat16(0.25f * (p[0] + p[1] + p[W_] + p[W_ + 1]));
}

// ---------------- bilinear 56->112 upsample + weighted combine (in place) ---
__global__ void combine_upsample() {
    int i = blockIdx.x * blockDim.x + threadIdx.x;
    if (i >= B_ * CHW_) return;
    int xo = i % W_;
    int yo = (i / W_) % H_;
    int bc = i / HW_;
    int ya, yb; float wya, wyb;
    if (yo & 1) { ya = yo >> 1; yb = min(ya + 1, TG_ - 1); wya = 0.75f; wyb = 0.25f; }
    else        { yb = yo >> 1; ya = max(yb - 1, 0);       wya = 0.25f; wyb = 0.75f; }
    int xa, xb; float wxa, wxb;
    if (xo & 1) { xa = xo >> 1; xb = min(xa + 1, TG_ - 1); wxa = 0.75f; wxb = 0.25f; }
    else        { xb = xo >> 1; xa = max(xb - 1, 0);       wxa = 0.25f; wxb = 0.75f; }
    const float* hg = g_hg + (size_t)bc * AG_;
    float g = wya * (wxa * hg[ya * TG_ + xa] + wxb * hg[ya * TG_ + xb])
            + wyb * (wxa * hg[yb * TG_ + xa] + wxb * hg[yb * TG_ + xb]);
    g_hp[i] = 0.75f * g_hp[i] + 0.25f * g;
}

// ---------------- launcher ---------------------------------------------------
extern "C" void kernel_launch(void* const* d_in, const int* in_sizes, int n_in,
                              void* d_out, int out_size) {
    const float* x  = (const float*)d_in[0];
    const float* gw = (const float*)d_in[1];
    const float* gb = (const float*)d_in[2];
    const float* wq = (const float*)d_in[3];
    const float* bq = (const float*)d_in[4];
    const float* wk = (const float*)d_in[5];
    const float* bk = (const float*)d_in[6];
    const float* wv = (const float*)d_in[7];
    const float* bv = (const float*)d_in[8];
    const float* wp = (const float*)d_in[9];
    float* out = (float*)d_out;

    float* p_xn;  cudaGetSymbolAddress((void**)&p_xn,  g_xn);
    float* p_q;   cudaGetSymbolAddress((void**)&p_q,   g_q);
    float* p_k;   cudaGetSymbolAddress((void**)&p_k,   g_k);
    float* p_v;   cudaGetSymbolAddress((void**)&p_v,   g_v);
    __nv_bfloat16* p_qpt; cudaGetSymbolAddress((void**)&p_qpt, g_qpt);
    __nv_bfloat16* p_kpt; cudaGetSymbolAddress((void**)&p_kpt, g_kpt);
    __nv_bfloat16* p_vpb; cudaGetSymbolAddress((void**)&p_vpb, g_vpb);
    float* p_sp;  cudaGetSymbolAddress((void**)&p_sp,  g_sp);
    float* p_spt; cudaGetSymbolAddress((void**)&p_spt, g_spart);
    __nv_bfloat16* p_sgb; cudaGetSymbolAddress((void**)&p_sgb, g_sgb);
    float* p_hp;  cudaGetSymbolAddress((void**)&p_hp,  g_hp);
    float* p_hg;  cudaGetSymbolAddress((void**)&p_hg,  g_hg);
    float* p_z;   cudaGetSymbolAddress((void**)&p_z,   g_z);

    // dynamic smem sizes (tf32 KC=32): MN-major tile 128*36 fl, K-major 32*136 fl
    const int SM_00 = 2 * (128*36 + 32*136) * 4;   // 71680
    const int SM_10 = 2 * (32*136 + 32*136) * 4;   // 69632
    const int SM_01 = 2 * (128*36 + 128*36) * 4;   // 73728
    const int SM_BF = 2 * 2 * 128 * 36 * 4;        // 73728 (bf16 KC=64)

    cudaFuncSetAttribute(gemm_tc<0,0,true ,false>, cudaFuncAttributeMaxDynamicSharedMemorySize, SM_00);
    cudaFuncSetAttribute(gemm_tc<0,0,false,true >, cudaFuncAttributeMaxDynamicSharedMemorySize, SM_00);
    cudaFuncSetAttribute(gemm_tc<1,0,false,false>, cudaFuncAttributeMaxDynamicSharedMemorySize, SM_10);
    cudaFuncSetAttribute(gemm_tc<0,1,false,false>, cudaFuncAttributeMaxDynamicSharedMemorySize, SM_01);
    cudaFuncSetAttribute(gemm_bf<true ,false>,     cudaFuncAttributeMaxDynamicSharedMemorySize, SM_BF);
    cudaFuncSetAttribute(gemm_bf<false,true >,     cudaFuncAttributeMaxDynamicSharedMemorySize, SM_BF);

    // 1) GroupNorm
    gn_stats1<<<dim3(128, B_), 256>>>(x);
    gn_stats2<<<B_, 128>>>();
    gn_apply<<<cdiv(B_ * CHW_ / 4, 256), 256>>>(x, gw, gb);

    // 2) Q/K/V projections (tf32)
    dim3 gproj(cdiv(HW_, 128), cdiv(C_, 128), B_);
    gemm_tc<0,0,true,false><<<gproj, 256, SM_00>>>(wq, 0, p_xn, CHW_, p_q, CHW_,
                                            bq, nullptr, 0, C_, HW_, C_, 1, 1.f);
    gemm_tc<0,0,true,false><<<gproj, 256, SM_00>>>(wk, 0, p_xn, CHW_, p_k, CHW_,
                                            bk, nullptr, 0, C_, HW_, C_, 1, 1.f);
    gemm_tc<0,0,true,false><<<gproj, 256, SM_00>>>(wv, 0, p_xn, CHW_, p_v, CHW_,
                                            bv, nullptr, 0, C_, HW_, C_, 1, 1.f);

    // 3) pools (bf16, q/k transposed) + zero Z
    dim3 gpt(AG_ / 32, C_ / 32, B_);
    pool2x2_T<<<gpt, 256>>>(p_q, p_qpt);
    pool2x2_T<<<gpt, 256>>>(p_k, p_kpt);
    pool2x2_bf<<<cdiv(B_ * C_ * AG_, 256), 256>>>(p_v, p_vpb);
    zero_buf<<<cdiv(B_ * AG_, 256), 256>>>(p_z, B_ * AG_);

    // 4) Patch attention (tf32): scores (split-K) -> reduce -> softmax -> AV
    dim3 gps(cdiv(P_, 128), cdiv(P_, 128), B_ * NSPLIT_PS);
    gemm_tc<1,0,false,false><<<gps, 256, SM_10>>>(p_q, CHW_, p_k, CHW_,
                                           p_spt, (size_t)P_ * P_,
                                           nullptr, nullptr, 0,
                                           P_, P_, C_ * S_, NSPLIT_PS, 1.f / 128.f);
    reduce_splits<<<dim3(cdiv(P_ * P_, 256), B_), 256>>>(p_spt, p_sp, P_ * P_, NSPLIT_PS);
    softmax_rows<<<B_ * P_, 256>>>(p_sp, P_);
    dim3 gpo(cdiv(P_, 128), cdiv(C_ * S_, 128), B_);
    gemm_tc<0,1,false,false><<<gpo, 256, SM_01>>>(p_v, CHW_, p_sp, (size_t)P_ * P_,
                                           p_hp, CHW_, nullptr, nullptr, 0,
                                           C_ * S_, P_, P_, 1, 1.f);

    // 5) Global attention (bf16): E=exp(S)+Z fused -> AV scaled by 1/Z fused
    dim3 ggs(cdiv(AG_, 128), cdiv(AG_, 128), B_);
    gemm_bf<true,false><<<ggs, 256, SM_BF>>>(p_qpt, (size_t)AG_ * C_, p_kpt, (size_t)AG_ * C_,
                                             p_sgb, (size_t)AG_ * AG_, p_z, AG_,
                                             AG_, AG_, C_, 1.f / 16.f);
    dim3 ggo(cdiv(AG_, 128), cdiv(C_, 128), B_);
    gemm_bf<false,true><<<ggo, 256, SM_BF>>>(p_vpb, (size_t)C_ * AG_, p_sgb, (size_t)AG_ * AG_,
                                             p_hg, (size_t)C_ * AG_, p_z, AG_,
                                             C_, AG_, AG_, 1.f);

    // 6) combine 0.75*patch + 0.25*bilinear_up(global)
    combine_upsample<<<cdiv(B_ * CHW_, 256), 256>>>();

    // 7) out = x + Wproj @ h (tf32)
    gemm_tc<0,0,false,true><<<gproj, 256, SM_00>>>(wp, 0, p_hp, CHW_, out, CHW_,
                                            nullptr, x, CHW_, C_, HW_, C_, 1, 1.f);
}